// round 1
// baseline (speedup 1.0000x reference)
#include <cuda_runtime.h>
#include <cuda_fp16.h>
#include <math.h>

// ---------------- problem constants ----------------
#define BATCH 32
#define GDIM  1024
#define CDIM  256
#define FDIM  512
#define LTOK  4096
#define NH    8
#define DHEAD 64
#define LN_EPS_C 1e-5f
#define BN_EPS_C 1e-5f
#define ATT_SCALE 0.125f     // 1/sqrt(64)
#define NCH   8              // l-chunks for weighted-sum partials
#define LCH   (LTOK/NCH)     // 512

// ---------------- device scratch (no cudaMalloc allowed) ----------------
__device__ float  g_g[BATCH*FDIM];              // normalized global feature
__device__ float  g_u[BATCH*NH*FDIM];           // per-head folded query: u = q @ Wk_head
__device__ float  g_cb[BATCH*NH];               // q . bk per head
__device__ float  g_Wlt[CDIM*FDIM];             // Wl transposed (c-major)
__device__ float  g_sA[FDIM];                   // folded BN scale
__device__ float  g_tA[FDIM];                   // folded BN shift
__device__ __half g_x[(size_t)BATCH*LTOK*FDIM]; // normalized local tokens (128MB)
__device__ float  g_scores[BATCH*NH*LTOK];      // logits -> softmaxed in place
__device__ float  g_wpart[BATCH*NCH*NH*FDIM];   // partial attn-weighted sums

// ---------------- helpers ----------------
__device__ __forceinline__ float block_sum_512(float v, volatile float* red) {
    int t = threadIdx.x;
#pragma unroll
    for (int o = 16; o; o >>= 1) v += __shfl_xor_sync(0xffffffffu, v, o);
    if ((t & 31) == 0) red[t >> 5] = v;
    __syncthreads();
    float r = 0.f;
    if (t < 32) {
        r = (t < 16) ? red[t] : 0.f;
#pragma unroll
        for (int o = 8; o; o >>= 1) r += __shfl_xor_sync(0xffffffffu, r, o);
        if (t == 0) red[0] = r;
    }
    __syncthreads();
    r = red[0];
    __syncthreads();
    return r;
}

// ---------------- kernel T: transpose Wl, fold BN ----------------
__global__ void prep_kernel(const float* __restrict__ Wl,
                            const float* __restrict__ bn_g, const float* __restrict__ bn_b,
                            const float* __restrict__ bn_m, const float* __restrict__ bn_v) {
    int c = blockIdx.x;          // 0..255
    int f = threadIdx.x;         // 0..511
    g_Wlt[c*FDIM + f] = Wl[f*CDIM + c];
    if (c == 0) {
        float s = bn_g[f] * rsqrtf(bn_v[f] + BN_EPS_C);
        g_sA[f] = s;
        g_tA[f] = bn_b[f] - bn_m[f]*s;
    }
}

// ---------------- kernel A: global branch + folded query ----------------
__global__ __launch_bounds__(512) void global_kernel(
    const float* __restrict__ gf, const float* __restrict__ Wg, const float* __restrict__ bg,
    const float* __restrict__ gn_g, const float* __restrict__ gn_b,
    const float* __restrict__ Wq, const float* __restrict__ bq,
    const float* __restrict__ Wk, const float* __restrict__ bk)
{
    __shared__ __align__(16) float sg[GDIM];
    __shared__ __align__(16) float s_g[FDIM];
    __shared__ __align__(16) float s_q[FDIM];
    __shared__ float red[16];
    int b = blockIdx.x, t = threadIdx.x;
    sg[t]       = gf[b*GDIM + t];
    sg[t + 512] = gf[b*GDIM + t + 512];
    __syncthreads();

    // pre = global @ Wg^T + bg   (one output feature per thread)
    float acc = bg[t];
    {
        const float4* w4 = (const float4*)(Wg + (size_t)t*GDIM);
        const float4* x4 = (const float4*)sg;
#pragma unroll 8
        for (int k = 0; k < GDIM/4; k++) {
            float4 w = w4[k], x = x4[k];
            acc += w.x*x.x + w.y*x.y + w.z*x.z + w.w*x.w;
        }
    }
    // LayerNorm over 512
    float sum  = block_sum_512(acc, red);
    float sumq = block_sum_512(acc*acc, red);
    float mean = sum * (1.f/FDIM);
    float rstd = rsqrtf(sumq*(1.f/FDIM) - mean*mean + LN_EPS_C);
    float gval = (acc - mean)*rstd*gn_g[t] + gn_b[t];
    s_g[t] = gval;
    g_g[b*FDIM + t] = gval;
    __syncthreads();

    // q = g @ Wq^T + bq
    float qv = bq[t];
    {
        const float4* w4 = (const float4*)(Wq + (size_t)t*FDIM);
        const float4* x4 = (const float4*)s_g;
#pragma unroll 8
        for (int k = 0; k < FDIM/4; k++) {
            float4 w = w4[k], x = x4[k];
            qv += w.x*x.x + w.y*x.y + w.z*x.z + w.w*x.w;
        }
    }
    s_q[t] = qv;
    __syncthreads();

    // u[h][c] = sum_d q[h*64+d] * Wk[h*64+d][c]   (c = t, coalesced over threads)
    int c = t;
#pragma unroll
    for (int h = 0; h < NH; h++) {
        float a = 0.f;
#pragma unroll 16
        for (int d = 0; d < DHEAD; d++)
            a += s_q[h*DHEAD + d] * __ldg(&Wk[(size_t)(h*DHEAD + d)*FDIM + c]);
        g_u[(b*NH + h)*FDIM + c] = a;
    }
    if (t < NH) {
        float a = 0.f;
#pragma unroll 16
        for (int d = 0; d < DHEAD; d++) a += s_q[t*DHEAD + d] * bk[t*DHEAD + d];
        g_cb[b*NH + t] = a;
    }
}

// ---------------- kernel B: conv1x1 + BN + ReLU + LN + scores (the big one) ----------------
#define TT 64
#define KC 16
__global__ __launch_bounds__(512, 1) void local_kernel(
    const float* __restrict__ lf,
    const float* __restrict__ ln_g, const float* __restrict__ ln_b)
{
    __shared__ __align__(16) float Ws[KC][FDIM];   // 32KB (reused for u/params in epilogue)
    __shared__ __align__(16) float Xs[KC][TT];     // 4KB
    int b  = blockIdx.y;
    int l0 = blockIdx.x * TT;
    int t  = threadIdx.x;
    int fg = t & 31;    // lane -> feature group (features fg + 32*j)
    int tg = t >> 5;    // warp -> 4-token group

    float acc[4][16];
#pragma unroll
    for (int a = 0; a < 4; a++)
#pragma unroll
        for (int j = 0; j < 16; j++) acc[a][j] = 0.f;

    const float* lfb = lf + (size_t)b*CDIM*LTOK;

    for (int c0 = 0; c0 < CDIM; c0 += KC) {
        // load W chunk (contiguous, coalesced)
        {
            const float4* src = (const float4*)(g_Wlt + (size_t)c0*FDIM);
            float4* dst = (float4*)(&Ws[0][0]);
#pragma unroll
            for (int i = 0; i < 4; i++) dst[t + 512*i] = src[t + 512*i];
        }
        // load X chunk
        if (t < 256) {
            int row = t >> 4, col = (t & 15) * 4;
            *(float4*)&Xs[row][col] = *(const float4*)&lfb[(size_t)(c0 + row)*LTOK + l0 + col];
        }
        __syncthreads();
#pragma unroll
        for (int kk = 0; kk < KC; kk++) {
            float4 xv = *(float4*)&Xs[kk][tg*4];
#pragma unroll
            for (int j = 0; j < 16; j++) {
                float w = Ws[kk][fg + 32*j];
                acc[0][j] = fmaf(w, xv.x, acc[0][j]);
                acc[1][j] = fmaf(w, xv.y, acc[1][j]);
                acc[2][j] = fmaf(w, xv.z, acc[2][j]);
                acc[3][j] = fmaf(w, xv.w, acc[3][j]);
            }
        }
        __syncthreads();
    }

    // ---- epilogue: stash u and per-feature params in smem (reuse Ws) ----
    float* u_s = &Ws[0][0];          // 4096 floats
    float* prm = &Ws[0][0] + 4096;   // sA | tA | ln_g | ln_b (4 x 512)
#pragma unroll
    for (int i = 0; i < 8; i++) u_s[t + 512*i] = g_u[(size_t)b*NH*FDIM + t + 512*i];
    prm[t]        = g_sA[t];
    prm[512 + t]  = g_tA[t];
    prm[1024 + t] = ln_g[t];
    prm[1536 + t] = ln_b[t];
    __syncthreads();

    int hh = fg & 7, tk = fg >> 3;
    float out_score = 0.f;

#pragma unroll
    for (int tok = 0; tok < 4; tok++) {
        // BN (folded) + ReLU, accumulate LN stats
        float s = 0.f, ss = 0.f;
#pragma unroll
        for (int j = 0; j < 16; j++) {
            int f = fg + 32*j;
            float r = fmaxf(fmaf(acc[tok][j], prm[f], prm[512 + f]), 0.f);
            acc[tok][j] = r; s += r; ss += r*r;
        }
#pragma unroll
        for (int o = 16; o; o >>= 1) {
            s  += __shfl_xor_sync(0xffffffffu, s,  o);
            ss += __shfl_xor_sync(0xffffffffu, ss, o);
        }
        float mean = s * (1.f/FDIM);
        float rstd = rsqrtf(ss*(1.f/FDIM) - mean*mean + LN_EPS_C);
#pragma unroll
        for (int j = 0; j < 16; j++) {
            int f = fg + 32*j;
            acc[tok][j] = fmaf((acc[tok][j] - mean)*rstd, prm[1024 + f], prm[1536 + f]);
        }
        // store x as fp16
        {
            __half* dst = g_x + ((size_t)(b*LTOK + l0 + tg*4 + tok))*FDIM;
#pragma unroll
            for (int j = 0; j < 16; j++) dst[fg + 32*j] = __float2half_rn(acc[tok][j]);
        }
        // score partials: p[h] = sum_f x_f * u[h][f]
        float p[8];
#pragma unroll
        for (int h = 0; h < 8; h++) p[h] = 0.f;
#pragma unroll
        for (int j = 0; j < 16; j++) {
            float xv = acc[tok][j];
            int f = fg + 32*j;
#pragma unroll
            for (int h = 0; h < 8; h++) p[h] = fmaf(xv, u_s[h*FDIM + f], p[h]);
        }
#pragma unroll
        for (int h = 0; h < 8; h++) {
#pragma unroll
            for (int o = 16; o; o >>= 1) p[h] += __shfl_xor_sync(0xffffffffu, p[h], o);
        }
        if (tk == tok) {
#pragma unroll
            for (int h = 0; h < 8; h++) if (h == hh) out_score = p[h];
        }
    }
    g_scores[(size_t)(b*NH + hh)*LTOK + l0 + tg*4 + tk] =
        (out_score + g_cb[b*NH + hh]) * ATT_SCALE;
}

// ---------------- kernel C: softmax over L per (b,h) ----------------
__global__ __launch_bounds__(256) void softmax_kernel() {
    int r = blockIdx.x;                      // b*8+h
    float* row = g_scores + (size_t)r*LTOK;
    __shared__ float red[8];
    int t = threadIdx.x;
    float v[16];
    float mx = -1e30f;
#pragma unroll
    for (int i = 0; i < 16; i++) { v[i] = row[t + 256*i]; mx = fmaxf(mx, v[i]); }
#pragma unroll
    for (int o = 16; o; o >>= 1) mx = fmaxf(mx, __shfl_xor_sync(0xffffffffu, mx, o));
    if ((t & 31) == 0) red[t >> 5] = mx;
    __syncthreads();
    if (t < 32) {
        float m = (t < 8) ? red[t] : -1e30f;
#pragma unroll
        for (int o = 4; o; o >>= 1) m = fmaxf(m, __shfl_xor_sync(0xffffffffu, m, o));
        if (t == 0) red[0] = m;
    }
    __syncthreads();
    mx = red[0];
    __syncthreads();
    float s = 0.f;
#pragma unroll
    for (int i = 0; i < 16; i++) { v[i] = __expf(v[i] - mx); s += v[i]; }
#pragma unroll
    for (int o = 16; o; o >>= 1) s += __shfl_xor_sync(0xffffffffu, s, o);
    if ((t & 31) == 0) red[t >> 5] = s;
    __syncthreads();
    if (t < 32) {
        float m = (t < 8) ? red[t] : 0.f;
#pragma unroll
        for (int o = 4; o; o >>= 1) m += __shfl_xor_sync(0xffffffffu, m, o);
        if (t == 0) red[0] = m;
    }
    __syncthreads();
    float inv = 1.f / red[0];
#pragma unroll
    for (int i = 0; i < 16; i++) row[t + 256*i] = v[i] * inv;
}

// ---------------- kernel D: w_part[b,ch,h,c] = sum_l attn * x ----------------
__global__ __launch_bounds__(256) void wsum_kernel() {
    int b = blockIdx.y, ch = blockIdx.x;
    int l0 = ch * LCH;
    __shared__ float at[NH][LCH];   // 16KB
    int t = threadIdx.x;
    for (int i = t; i < NH*LCH; i += 256) {
        int h = i >> 9, l = i & 511;
        at[h][l] = g_scores[(size_t)(b*NH + h)*LTOK + l0 + l];
    }
    __syncthreads();
    float acc[16];
#pragma unroll
    for (int i = 0; i < 16; i++) acc[i] = 0.f;
    const __half2* xp = (const __half2*)g_x + (size_t)(b*LTOK + l0)*(FDIM/2) + t;
#pragma unroll 4
    for (int l = 0; l < LCH; l++) {
        float2 xv = __half22float2(xp[(size_t)l*(FDIM/2)]);
#pragma unroll
        for (int h = 0; h < NH; h++) {
            float a = at[h][l];
            acc[2*h]   = fmaf(a, xv.x, acc[2*h]);
            acc[2*h+1] = fmaf(a, xv.y, acc[2*h+1]);
        }
    }
    float* wp = g_wpart + (size_t)((b*NCH + ch)*NH)*FDIM;
#pragma unroll
    for (int h = 0; h < NH; h++)
        *(float2*)&wp[h*FDIM + 2*t] = make_float2(acc[2*h], acc[2*h+1]);
}

// ---------------- kernel E: o/attended/gate/MLP/LN ----------------
__global__ __launch_bounds__(512) void fuse_kernel(
    const float* __restrict__ Wv, const float* __restrict__ bv,
    const float* __restrict__ Wo, const float* __restrict__ bo,
    const float* __restrict__ Wgate, const float* __restrict__ bgate,
    const float* __restrict__ We1, const float* __restrict__ be1,
    const float* __restrict__ We2, const float* __restrict__ be2,
    const float* __restrict__ eln_g, const float* __restrict__ eln_b,
    float* __restrict__ out)
{
    __shared__ __align__(16) float w_s[NH*FDIM];   // 16KB
    __shared__ __align__(16) float o_s[FDIM];
    __shared__ __align__(16) float att_s[FDIM];
    __shared__ __align__(16) float gs[FDIM];
    __shared__ __align__(16) float fu[FDIM];
    __shared__ __align__(16) float h1[2*FDIM];
    __shared__ float red[16];
    int b = blockIdx.x, t = threadIdx.x;

    for (int i = t; i < NH*FDIM; i += 512) {
        float s = 0.f;
#pragma unroll
        for (int ch = 0; ch < NCH; ch++)
            s += g_wpart[(size_t)((b*NCH + ch)*NH)*FDIM + i];
        w_s[i] = s;
    }
    gs[t] = g_g[b*FDIM + t];
    __syncthreads();

    // o[h*64+d] = w[h] . Wv[row] + bv
    {
        int h = t >> 6;
        float a = bv[t];
        const float4* wr = (const float4*)(Wv + (size_t)t*FDIM);
        const float4* ws = (const float4*)(w_s + h*FDIM);
#pragma unroll 8
        for (int k = 0; k < FDIM/4; k++) {
            float4 w = wr[k], x = ws[k];
            a += w.x*x.x + w.y*x.y + w.z*x.z + w.w*x.w;
        }
        o_s[t] = a;
    }
    __syncthreads();

    // attended = o @ Wo^T + bo
    {
        float a = bo[t];
        const float4* wr = (const float4*)(Wo + (size_t)t*FDIM);
        const float4* xs = (const float4*)o_s;
#pragma unroll 8
        for (int k = 0; k < FDIM/4; k++) {
            float4 w = wr[k], x = xs[k];
            a += w.x*x.x + w.y*x.y + w.z*x.z + w.w*x.w;
        }
        att_s[t] = a;
    }
    __syncthreads();

    // gate + fused
    {
        float z = bgate[t];
        const float4* wr = (const float4*)(Wgate + (size_t)t*2*FDIM);
        const float4* xg = (const float4*)gs;
        const float4* xa = (const float4*)att_s;
#pragma unroll 8
        for (int k = 0; k < FDIM/4; k++) {
            float4 w = wr[k], x = xg[k];
            z += w.x*x.x + w.y*x.y + w.z*x.z + w.w*x.w;
        }
#pragma unroll 8
        for (int k = 0; k < FDIM/4; k++) {
            float4 w = wr[FDIM/4 + k], x = xa[k];
            z += w.x*x.x + w.y*x.y + w.z*x.z + w.w*x.w;
        }
        float gate = 1.f / (1.f + expf(-z));
        fu[t] = gate*gs[t] + (1.f - gate)*att_s[t];
    }
    __syncthreads();

    // h1 = gelu(fused @ We1^T + be1)  (exact erf gelu)
#pragma unroll
    for (int rr = 0; rr < 2; rr++) {
        int j = t + 512*rr;
        float a = be1[j];
        const float4* wr = (const float4*)(We1 + (size_t)j*FDIM);
        const float4* xs = (const float4*)fu;
#pragma unroll 8
        for (int k = 0; k < FDIM/4; k++) {
            float4 w = wr[k], x = xs[k];
            a += w.x*x.x + w.y*x.y + w.z*x.z + w.w*x.w;
        }
        h1[j] = 0.5f * a * (1.f + erff(a * 0.70710678118654752f));
    }
    __syncthreads();

    // out = LN(h1 @ We2^T + be2)
    float v = be2[t];
    {
        const float4* wr = (const float4*)(We2 + (size_t)t*2*FDIM);
        const float4* xs = (const float4*)h1;
#pragma unroll 8
        for (int k = 0; k < 2*FDIM/4; k++) {
            float4 w = wr[k], x = xs[k];
            v += w.x*x.x + w.y*x.y + w.z*x.z + w.w*x.w;
        }
    }
    float sum  = block_sum_512(v, red);
    float sumq = block_sum_512(v*v, red);
    float mean = sum * (1.f/FDIM);
    float rstd = rsqrtf(sumq*(1.f/FDIM) - mean*mean + LN_EPS_C);
    out[b*FDIM + t] = (v - mean)*rstd*eln_g[t] + eln_b[t];
}

// ---------------- launch ----------------
extern "C" void kernel_launch(void* const* d_in, const int* in_sizes, int n_in,
                              void* d_out, int out_size) {
    const float* global_feat = (const float*)d_in[0];
    const float* local_feat  = (const float*)d_in[1];
    const float* Wg    = (const float*)d_in[2];
    const float* bg    = (const float*)d_in[3];
    const float* gn_g  = (const float*)d_in[4];
    const float* gn_b  = (const float*)d_in[5];
    const float* Wl    = (const float*)d_in[6];
    const float* bn_g  = (const float*)d_in[7];
    const float* bn_b  = (const float*)d_in[8];
    const float* bn_m  = (const float*)d_in[9];
    const float* bn_v  = (const float*)d_in[10];
    const float* ln_g  = (const float*)d_in[11];
    const float* ln_b  = (const float*)d_in[12];
    const float* Wq    = (const float*)d_in[13];
    const float* bq    = (const float*)d_in[14];
    const float* Wk    = (const float*)d_in[15];
    const float* bk    = (const float*)d_in[16];
    const float* Wv    = (const float*)d_in[17];
    const float* bv    = (const float*)d_in[18];
    const float* Wo    = (const float*)d_in[19];
    const float* bo    = (const float*)d_in[20];
    const float* Wgate = (const float*)d_in[21];
    const float* bgate = (const float*)d_in[22];
    const float* We1   = (const float*)d_in[23];
    const float* be1   = (const float*)d_in[24];
    const float* We2   = (const float*)d_in[25];
    const float* be2   = (const float*)d_in[26];
    const float* eln_g = (const float*)d_in[27];
    const float* eln_b = (const float*)d_in[28];
    float* out = (float*)d_out;

    prep_kernel<<<CDIM, FDIM>>>(Wl, bn_g, bn_b, bn_m, bn_v);
    global_kernel<<<BATCH, 512>>>(global_feat, Wg, bg, gn_g, gn_b, Wq, bq, Wk, bk);
    local_kernel<<<dim3(LTOK/TT, BATCH), 512>>>(local_feat, ln_g, ln_b);
    softmax_kernel<<<BATCH*NH, 256>>>();
    wsum_kernel<<<dim3(NCH, BATCH), 256>>>();
    fuse_kernel<<<BATCH, 512>>>(Wv, bv, Wo, bo, Wgate, bgate,
                                We1, be1, We2, be2, eln_g, eln_b, out);
}

// round 6
// speedup vs baseline: 1.5962x; 1.5962x over previous
#include <cuda_runtime.h>
#include <cuda_fp16.h>
#include <math.h>

// ---------------- problem constants ----------------
#define BATCH 32
#define GDIM  1024
#define CDIM  256
#define FDIM  512
#define LTOK  4096
#define NH    8
#define DHEAD 64
#define LN_EPS_C 1e-5f
#define BN_EPS_C 1e-5f
#define ATT_SCALE 0.125f     // 1/sqrt(64)
#define NCH   8              // l-chunks for weighted-sum partials
#define LCH   (LTOK/NCH)     // 512

// ---- local_kernel (tensor-core) geometry ----
#define TT    64             // tokens per CTA
#define KB    32             // k-chunk
#define ASTR  72             // As row stride (u32) -> bank-conflict-free frags
#define BSTR  520            // Bs row stride (u32) -> bank-conflict-free frags
#define CSTR  520            // Cs row stride (f32)
#define CS_U32   (TT*CSTR)                   // 33280 floats = 133120 B
#define SMEM_TOTAL_B ((CS_U32 + NH*FDIM + 4*FDIM) * 4)   // 157696 B

// ---------------- device scratch (no cudaMalloc allowed) ----------------
__device__ float  g_g[BATCH*FDIM];              // normalized global feature
__device__ float  g_u[BATCH*NH*FDIM];           // per-head folded query: u = q @ Wk_head
__device__ float  g_cb[BATCH*NH];               // q . bk per head
__device__ float  g_Wlt[CDIM*FDIM];             // Wl transposed (c-major)
__device__ float  g_sA[FDIM];                   // folded BN scale
__device__ float  g_tA[FDIM];                   // folded BN shift
__device__ __half g_x[(size_t)BATCH*LTOK*FDIM]; // normalized local tokens (128MB)
__device__ float  g_scores[BATCH*NH*LTOK];      // logits -> softmaxed in place
__device__ float  g_wpart[BATCH*NCH*NH*FDIM];   // partial attn-weighted sums

// ---------------- helpers ----------------
__device__ __forceinline__ float block_sum_512(float v, volatile float* red) {
    int t = threadIdx.x;
#pragma unroll
    for (int o = 16; o; o >>= 1) v += __shfl_xor_sync(0xffffffffu, v, o);
    if ((t & 31) == 0) red[t >> 5] = v;
    __syncthreads();
    float r = 0.f;
    if (t < 32) {
        r = (t < 16) ? red[t] : 0.f;
#pragma unroll
        for (int o = 8; o; o >>= 1) r += __shfl_xor_sync(0xffffffffu, r, o);
        if (t == 0) red[0] = r;
    }
    __syncthreads();
    r = red[0];
    __syncthreads();
    return r;
}

__device__ __forceinline__ unsigned f2tf32(float x) {
    unsigned r;
    asm("cvt.rna.tf32.f32 %0, %1;" : "=r"(r) : "f"(x));
    return r;
}

__device__ __forceinline__ void mma_tf32(float c[4], const unsigned a[4], const unsigned b[2]) {
    asm("mma.sync.aligned.m16n8k8.row.col.f32.tf32.tf32.f32 "
        "{%0,%1,%2,%3}, {%4,%5,%6,%7}, {%8,%9}, {%0,%1,%2,%3};"
        : "+f"(c[0]), "+f"(c[1]), "+f"(c[2]), "+f"(c[3])
        : "r"(a[0]), "r"(a[1]), "r"(a[2]), "r"(a[3]), "r"(b[0]), "r"(b[1]));
}

// ---------------- kernel T: transpose Wl, fold BN ----------------
__global__ void prep_kernel(const float* __restrict__ Wl,
                            const float* __restrict__ bn_g, const float* __restrict__ bn_b,
                            const float* __restrict__ bn_m, const float* __restrict__ bn_v) {
    int c = blockIdx.x;          // 0..255
    int f = threadIdx.x;         // 0..511
    g_Wlt[c*FDIM + f] = Wl[f*CDIM + c];
    if (c == 0) {
        float s = bn_g[f] * rsqrtf(bn_v[f] + BN_EPS_C);
        g_sA[f] = s;
        g_tA[f] = bn_b[f] - bn_m[f]*s;
    }
}

// ---------------- kernel A: global branch + folded query ----------------
__global__ __launch_bounds__(512) void global_kernel(
    const float* __restrict__ gf, const float* __restrict__ Wg, const float* __restrict__ bg,
    const float* __restrict__ gn_g, const float* __restrict__ gn_b,
    const float* __restrict__ Wq, const float* __restrict__ bq,
    const float* __restrict__ Wk, const float* __restrict__ bk)
{
    __shared__ __align__(16) float sg[GDIM];
    __shared__ __align__(16) float s_g[FDIM];
    __shared__ __align__(16) float s_q[FDIM];
    __shared__ float red[16];
    int b = blockIdx.x, t = threadIdx.x;
    sg[t]       = gf[b*GDIM + t];
    sg[t + 512] = gf[b*GDIM + t + 512];
    __syncthreads();

    float acc = bg[t];
    {
        const float4* w4 = (const float4*)(Wg + (size_t)t*GDIM);
        const float4* x4 = (const float4*)sg;
#pragma unroll 8
        for (int k = 0; k < GDIM/4; k++) {
            float4 w = w4[k], x = x4[k];
            acc += w.x*x.x + w.y*x.y + w.z*x.z + w.w*x.w;
        }
    }
    float sum  = block_sum_512(acc, red);
    float sumq = block_sum_512(acc*acc, red);
    float mean = sum * (1.f/FDIM);
    float rstd = rsqrtf(sumq*(1.f/FDIM) - mean*mean + LN_EPS_C);
    float gval = (acc - mean)*rstd*gn_g[t] + gn_b[t];
    s_g[t] = gval;
    g_g[b*FDIM + t] = gval;
    __syncthreads();

    float qv = bq[t];
    {
        const float4* w4 = (const float4*)(Wq + (size_t)t*FDIM);
        const float4* x4 = (const float4*)s_g;
#pragma unroll 8
        for (int k = 0; k < FDIM/4; k++) {
            float4 w = w4[k], x = x4[k];
            qv += w.x*x.x + w.y*x.y + w.z*x.z + w.w*x.w;
        }
    }
    s_q[t] = qv;
    __syncthreads();

    int c = t;
#pragma unroll
    for (int h = 0; h < NH; h++) {
        float a = 0.f;
#pragma unroll 16
        for (int d = 0; d < DHEAD; d++)
            a += s_q[h*DHEAD + d] * __ldg(&Wk[(size_t)(h*DHEAD + d)*FDIM + c]);
        g_u[(b*NH + h)*FDIM + c] = a;
    }
    if (t < NH) {
        float a = 0.f;
#pragma unroll 16
        for (int d = 0; d < DHEAD; d++) a += s_q[t*DHEAD + d] * bk[t*DHEAD + d];
        g_cb[b*NH + t] = a;
    }
}

// ---------------- kernel B: conv1x1 GEMM on tensor cores + BN + ReLU + LN + scores ----------------
// Software-pipelined: chunk i+1 is prefetched into registers while MMAs run on
// chunk i from shared memory (1 CTA/SM -> no other CTA hides the DRAM latency).
__global__ __launch_bounds__(512, 1) void local_kernel(
    const float* __restrict__ lf,
    const float* __restrict__ ln_g, const float* __restrict__ ln_b)
{
    extern __shared__ __align__(16) float smem[];
    float*    Cs  = smem;                        // [TT][CSTR]  (epilogue)
    unsigned* As  = (unsigned*)smem;             // [KB][ASTR]  (overlaid staging)
    unsigned* Bs  = (unsigned*)smem + KB*ASTR;   // [KB][BSTR]
    float*    u_s = smem + CS_U32;               // [NH*FDIM]
    float*    prm = smem + CS_U32 + NH*FDIM;     // sA | tA | ln_g | ln_b

    const int b  = blockIdx.y;
    const int l0 = blockIdx.x * TT;
    const int t  = threadIdx.x;
    const int wid  = t >> 5;
    const int lane = t & 31;
    const int warp_m = wid & 1;        // token half (32)
    const int warp_n = wid >> 1;       // feature group (64)
    const int qrow = lane >> 2;        // 0..7
    const int qcol = lane & 3;         // 0..3

    const float* lfb = lf + (size_t)b*CDIM*LTOK;

    // per-thread staging coordinates (fixed across chunks)
    const int sa_c = t >> 4;                 // 0..31
    const int sa_i = (t & 15) * 4;           // 0..60

    float acc[2][8][4];
#pragma unroll
    for (int mt = 0; mt < 2; mt++)
#pragma unroll
        for (int nt = 0; nt < 8; nt++)
#pragma unroll
            for (int i = 0; i < 4; i++) acc[mt][nt][i] = 0.f;

    // ---- prologue: prefetch chunk 0 into registers ----
    float4 av;
    float4 bv[8];
    av = *(const float4*)&lfb[(size_t)sa_c*LTOK + l0 + sa_i];
#pragma unroll
    for (int it = 0; it < 8; it++) {
        int idx = it*512 + t;
        int c2 = idx >> 7, fo = (idx & 127) * 4;
        bv[it] = *(const float4*)&g_Wlt[(size_t)c2*FDIM + fo];
    }

    // ---- mainloop over K in chunks of KB ----
    for (int c0 = 0; c0 < CDIM; c0 += KB) {
        // commit staged registers to smem (tf32 convert at store)
        *(uint4*)&As[sa_c*ASTR + sa_i] =
            make_uint4(f2tf32(av.x), f2tf32(av.y), f2tf32(av.z), f2tf32(av.w));
#pragma unroll
        for (int it = 0; it < 8; it++) {
            int idx = it*512 + t;
            int c2 = idx >> 7, fo = (idx & 127) * 4;
            *(uint4*)&Bs[c2*BSTR + fo] =
                make_uint4(f2tf32(bv[it].x), f2tf32(bv[it].y), f2tf32(bv[it].z), f2tf32(bv[it].w));
        }
        __syncthreads();

        // prefetch next chunk while MMAs below chew on this one
        const int cn = c0 + KB;
        if (cn < CDIM) {
            av = *(const float4*)&lfb[(size_t)(cn + sa_c)*LTOK + l0 + sa_i];
#pragma unroll
            for (int it = 0; it < 8; it++) {
                int idx = it*512 + t;
                int c2 = idx >> 7, fo = (idx & 127) * 4;
                bv[it] = *(const float4*)&g_Wlt[(size_t)(cn + c2)*FDIM + fo];
            }
        }

#pragma unroll
        for (int ks = 0; ks < KB/8; ks++) {
            const int kk = ks * 8;
            unsigned afr[2][4], bfr[8][2];
#pragma unroll
            for (int mt = 0; mt < 2; mt++) {
                int row = warp_m*32 + mt*16 + qrow;
                afr[mt][0] = As[(kk + qcol    )*ASTR + row    ];
                afr[mt][1] = As[(kk + qcol    )*ASTR + row + 8];
                afr[mt][2] = As[(kk + qcol + 4)*ASTR + row    ];
                afr[mt][3] = As[(kk + qcol + 4)*ASTR + row + 8];
            }
#pragma unroll
            for (int nt = 0; nt < 8; nt++) {
                int f = warp_n*64 + nt*8 + qrow;
                bfr[nt][0] = Bs[(kk + qcol    )*BSTR + f];
                bfr[nt][1] = Bs[(kk + qcol + 4)*BSTR + f];
            }
#pragma unroll
            for (int mt = 0; mt < 2; mt++)
#pragma unroll
                for (int nt = 0; nt < 8; nt++)
                    mma_tf32(acc[mt][nt], afr[mt], bfr[nt]);
        }
        __syncthreads();
    }

    // ---- spill accumulators to Cs (mma layout -> [token][feature]) ----
#pragma unroll
    for (int mt = 0; mt < 2; mt++) {
#pragma unroll
        for (int nt = 0; nt < 8; nt++) {
            int row = warp_m*32 + mt*16 + qrow;
            int col = warp_n*64 + nt*8 + 2*qcol;
            *(float2*)&Cs[ row     *CSTR + col] = make_float2(acc[mt][nt][0], acc[mt][nt][1]);
            *(float2*)&Cs[(row + 8)*CSTR + col] = make_float2(acc[mt][nt][2], acc[mt][nt][3]);
        }
    }
    // load u and per-feature params (disjoint smem regions)
#pragma unroll
    for (int i = 0; i < 8; i++) u_s[t + 512*i] = g_u[(size_t)b*NH*FDIM + t + 512*i];
    prm[t]        = g_sA[t];
    prm[512 + t]  = g_tA[t];
    prm[1024 + t] = ln_g[t];
    prm[1536 + t] = ln_b[t];
    __syncthreads();

    // ---- per-token BN + ReLU + LN, fp16 stash (warp wid owns tokens wid*4..wid*4+3) ----
#pragma unroll
    for (int tok = 0; tok < 4; tok++) {
        int row = wid*4 + tok;
        float v[16];
        float s = 0.f, ss = 0.f;
#pragma unroll
        for (int j = 0; j < 16; j++) {
            int f = lane + 32*j;
            float r = fmaxf(fmaf(Cs[row*CSTR + f], prm[f], prm[512 + f]), 0.f);
            v[j] = r; s += r; ss += r*r;
        }
#pragma unroll
        for (int o = 16; o; o >>= 1) {
            s  += __shfl_xor_sync(0xffffffffu, s,  o);
            ss += __shfl_xor_sync(0xffffffffu, ss, o);
        }
        float mean = s * (1.f/FDIM);
        float rstd = rsqrtf(ss*(1.f/FDIM) - mean*mean + LN_EPS_C);
        __half* dst = g_x + ((size_t)(b*LTOK + l0 + row))*FDIM;
#pragma unroll
        for (int j = 0; j < 16; j++) {
            int f = lane + 32*j;
            float nx = fmaf((v[j] - mean)*rstd, prm[1024 + f], prm[1536 + f]);
            Cs[row*CSTR + f] = nx;
            dst[f] = __float2half_rn(nx);
        }
    }

    // ---- scores: p[tok][h] = x . u[h]  (1 LDS-u per 4 FMA) ----
    float p[4][8];
#pragma unroll
    for (int a = 0; a < 4; a++)
#pragma unroll
        for (int h = 0; h < 8; h++) p[a][h] = 0.f;
#pragma unroll
    for (int j = 0; j < 16; j++) {
        int f = lane + 32*j;
        float xv[4];
#pragma unroll
        for (int a = 0; a < 4; a++) xv[a] = Cs[(wid*4 + a)*CSTR + f];
#pragma unroll
        for (int h = 0; h < 8; h++) {
            float uv = u_s[h*FDIM + f];
#pragma unroll
            for (int a = 0; a < 4; a++) p[a][h] = fmaf(xv[a], uv, p[a][h]);
        }
    }
#pragma unroll
    for (int a = 0; a < 4; a++)
#pragma unroll
        for (int h = 0; h < 8; h++)
#pragma unroll
            for (int o = 16; o; o >>= 1)
                p[a][h] += __shfl_xor_sync(0xffffffffu, p[a][h], o);

    {
        int hh = lane & 7, tk = lane >> 3;
        float v = 0.f;
#pragma unroll
        for (int a = 0; a < 4; a++)
#pragma unroll
            for (int h = 0; h < 8; h++)
                if (a == tk && h == hh) v = p[a][h];
        g_scores[(size_t)(b*NH + hh)*LTOK + l0 + wid*4 + tk] =
            (v + g_cb[b*NH + hh]) * ATT_SCALE;
    }
}

// ---------------- kernel C: softmax over L per (b,h) ----------------
__global__ __launch_bounds__(256) void softmax_kernel() {
    int r = blockIdx.x;                      // b*8+h
    float* row = g_scores + (size_t)r*LTOK;
    __shared__ float red[8];
    int t = threadIdx.x;
    float v[16];
    float mx = -1e30f;
#pragma unroll
    for (int i = 0; i < 16; i++) { v[i] = row[t + 256*i]; mx = fmaxf(mx, v[i]); }
#pragma unroll
    for (int o = 16; o; o >>= 1) mx = fmaxf(mx, __shfl_xor_sync(0xffffffffu, mx, o));
    if ((t & 31) == 0) red[t >> 5] = mx;
    __syncthreads();
    if (t < 32) {
        float m = (t < 8) ? red[t] : -1e30f;
#pragma unroll
        for (int o = 4; o; o >>= 1) m = fmaxf(m, __shfl_xor_sync(0xffffffffu, m, o));
        if (t == 0) red[0] = m;
    }
    __syncthreads();
    mx = red[0];
    __syncthreads();
    float s = 0.f;
#pragma unroll
    for (int i = 0; i < 16; i++) { v[i] = __expf(v[i] - mx); s += v[i]; }
#pragma unroll
    for (int o = 16; o; o >>= 1) s += __shfl_xor_sync(0xffffffffu, s, o);
    if ((t & 31) == 0) red[t >> 5] = s;
    __syncthreads();
    if (t < 32) {
        float m = (t < 8) ? red[t] : 0.f;
#pragma unroll
        for (int o = 4; o; o >>= 1) m += __shfl_xor_sync(0xffffffffu, m, o);
        if (t == 0) red[0] = m;
    }
    __syncthreads();
    float inv = 1.f / red[0];
#pragma unroll
    for (int i = 0; i < 16; i++) row[t + 256*i] = v[i] * inv;
}

// ---------------- kernel D: w_part[b,ch,h,c] = sum_l attn * x ----------------
__global__ __launch_bounds__(256) void wsum_kernel() {
    int b = blockIdx.y, ch = blockIdx.x;
    int l0 = ch * LCH;
    __shared__ float at[NH][LCH];   // 16KB
    int t = threadIdx.x;
    for (int i = t; i < NH*LCH; i += 256) {
        int h = i >> 9, l = i & 511;
        at[h][l] = g_scores[(size_t)(b*NH + h)*LTOK + l0 + l];
    }
    __syncthreads();
    float acc[16];
#pragma unroll
    for (int i = 0; i < 16; i++) acc[i] = 0.f;
    const __half2* xp = (const __half2*)g_x + (size_t)(b*LTOK + l0)*(FDIM/2) + t;
#pragma unroll 4
    for (int l = 0; l < LCH; l++) {
        float2 xv = __half22float2(xp[(size_t)l*(FDIM/2)]);
#pragma unroll
        for (int h = 0; h < NH; h++) {
            float a = at[h][l];
            acc[2*h]   = fmaf(a, xv.x, acc[2*h]);
            acc[2*h+1] = fmaf(a, xv.y, acc[2*h+1]);
        }
    }
    float* wp = g_wpart + (size_t)((b*NCH + ch)*NH)*FDIM;
#pragma unroll
    for (int h = 0; h < NH; h++)
        *(float2*)&wp[h*FDIM + 2*t] = make_float2(acc[2*h], acc[2*h+1]);
}

// ---------------- kernel E: o/attended/gate/MLP/LN ----------------
__global__ __launch_bounds__(512) void fuse_kernel(
    const float* __restrict__ Wv, const float* __restrict__ bv,
    const float* __restrict__ Wo, const float* __restrict__ bo,
    const float* __restrict__ Wgate, const float* __restrict__ bgate,
    const float* __restrict__ We1, const float* __restrict__ be1,
    const float* __restrict__ We2, const float* __restrict__ be2,
    const float* __restrict__ eln_g, const float* __restrict__ eln_b,
    float* __restrict__ out)
{
    __shared__ __align__(16) float w_s[NH*FDIM];   // 16KB
    __shared__ __align__(16) float o_s[FDIM];
    __shared__ __align__(16) float att_s[FDIM];
    __shared__ __align__(16) float gs[FDIM];
    __shared__ __align__(16) float fu[FDIM];
    __shared__ __align__(16) float h1[2*FDIM];
    __shared__ float red[16];
    int b = blockIdx.x, t = threadIdx.x;

    for (int i = t; i < NH*FDIM; i += 512) {
        float s = 0.f;
#pragma unroll
        for (int ch = 0; ch < NCH; ch++)
            s += g_wpart[(size_t)((b*NCH + ch)*NH)*FDIM + i];
        w_s[i] = s;
    }
    gs[t] = g_g[b*FDIM + t];
    __syncthreads();

    {
        int h = t >> 6;
        float a = bv[t];
        const float4* wr = (const float4*)(Wv + (size_t)t*FDIM);
        const float4* ws = (const float4*)(w_s + h*FDIM);
#pragma unroll 8
        for (int k = 0; k < FDIM/4; k++) {
            float4 w = wr[k], x = ws[k];
            a += w.x*x.x + w.y*x.y + w.z*x.z + w.w*x.w;
        }
        o_s[t] = a;
    }
    __syncthreads();

    {
        float a = bo[t];
        const float4* wr = (const float4*)(Wo + (size_t)t*FDIM);
        const float4* xs = (const float4*)o_s;
#pragma unroll 8
        for (int k = 0; k < FDIM/4; k++) {
            float4 w = wr[k], x = xs[k];
            a += w.x*x.x + w.y*x.y + w.z*x.z + w.w*x.w;
        }
        att_s[t] = a;
    }
    __syncthreads();

    {
        float z = bgate[t];
        const float4* wr = (const float4*)(Wgate + (size_t)t*2*FDIM);
        const float4* xg = (const float4*)gs;
        const float4* xa = (const float4*)att_s;
#pragma unroll 8
        for (int k = 0; k < FDIM/4; k++) {
            float4 w = wr[k], x = xg[k];
            z += w.x*x.x + w.y*x.y + w.z*x.z + w.w*x.w;
        }
#pragma unroll 8
        for (int k = 0; k < FDIM/4; k++) {
            float4 w = wr[FDIM/4 + k], x = xa[k];
            z += w.x*x.x + w.y*x.y + w.z*x.z + w.w*x.w;
        }
        float gate = 1.f / (1.f + expf(-z));
        fu[t] = gate*gs[t] + (1.f - gate)*att_s[t];
    }
    __syncthreads();

#pragma unroll
    for (int rr = 0; rr < 2; rr++) {
        int j = t + 512*rr;
        float a = be1[j];
        const float4* wr = (const float4*)(We1 + (size_t)j*FDIM);
        const float4* xs = (const float4*)fu;
#pragma unroll 8
        for (int k = 0; k < FDIM/4; k++) {
            float4 w = wr[k], x = xs[k];
            a += w.x*x.x + w.y*x.y + w.z*x.z + w.w*x.w;
        }
        h1[j] = 0.5f * a * (1.f + erff(a * 0.70710678118654752f));
    }
    __syncthreads();

    float v = be2[t];
    {
        const float4* wr = (const float4*)(We2 + (size_t)t*2*FDIM);
        const float4* xs = (const float4*)h1;
#pragma unroll 8
        for (int k = 0; k < 2*FDIM/4; k++) {
            float4 w = wr[k], x = xs[k];
            v += w.x*x.x + w.y*x.y + w.z*x.z + w.w*x.w;
        }
    }
    float sum  = block_sum_512(v, red);
    float sumq = block_sum_512(v*v, red);
    float mean = sum * (1.f/FDIM);
    float rstd = rsqrtf(sumq*(1.f/FDIM) - mean*mean + LN_EPS_C);
    out[b*FDIM + t] = (v - mean)*rstd*eln_g[t] + eln_b[t];
}

// ---------------- launch ----------------
extern "C" void kernel_launch(void* const* d_in, const int* in_sizes, int n_in,
                              void* d_out, int out_size) {
    const float* global_feat = (const float*)d_in[0];
    const float* local_feat  = (const float*)d_in[1];
    const float* Wg    = (const float*)d_in[2];
    const float* bg    = (const float*)d_in[3];
    const float* gn_g  = (const float*)d_in[4];
    const float* gn_b  = (const float*)d_in[5];
    const float* Wl    = (const float*)d_in[6];
    const float* bn_g  = (const float*)d_in[7];
    const float* bn_b  = (const float*)d_in[8];
    const float* bn_m  = (const float*)d_in[9];
    const float* bn_v  = (const float*)d_in[10];
    const float* ln_g  = (const float*)d_in[11];
    const float* ln_b  = (const float*)d_in[12];
    const float* Wq    = (const float*)d_in[13];
    const float* bq    = (const float*)d_in[14];
    const float* Wk    = (const float*)d_in[15];
    const float* bk    = (const float*)d_in[16];
    const float* Wv    = (const float*)d_in[17];
    const float* bv    = (const float*)d_in[18];
    const float* Wo    = (const float*)d_in[19];
    const float* bo    = (const float*)d_in[20];
    const float* Wgate = (const float*)d_in[21];
    const float* bgate = (const float*)d_in[22];
    const float* We1   = (const float*)d_in[23];
    const float* be1   = (const float*)d_in[24];
    const float* We2   = (const float*)d_in[25];
    const float* be2   = (const float*)d_in[26];
    const float* eln_g = (const float*)d_in[27];
    const float* eln_b = (const float*)d_in[28];
    float* out = (float*)d_out;

    // No static guard (harness rule): unconditional, deterministic, not a
    // stream-ordered call so it is graph-capture safe.
    cudaFuncSetAttribute(local_kernel,
                         cudaFuncAttributeMaxDynamicSharedMemorySize, SMEM_TOTAL_B);

    prep_kernel<<<CDIM, FDIM>>>(Wl, bn_g, bn_b, bn_m, bn_v);
    global_kernel<<<BATCH, 512>>>(global_feat, Wg, bg, gn_g, gn_b, Wq, bq, Wk, bk);
    local_kernel<<<dim3(LTOK/TT, BATCH), 512, SMEM_TOTAL_B>>>(local_feat, ln_g, ln_b);
    softmax_kernel<<<BATCH*NH, 256>>>();
    wsum_kernel<<<dim3(NCH, BATCH), 256>>>();
    fuse_kernel<<<BATCH, 512>>>(Wv, bv, Wo, bo, Wgate, bgate,
                                We1, be1, We2, be2, eln_g, eln_b, out);
}

// round 9
// speedup vs baseline: 1.8716x; 1.1725x over previous
#include <cuda_runtime.h>
#include <cuda_fp16.h>
#include <math.h>

// ---------------- problem constants ----------------
#define BATCH 32
#define GDIM  1024
#define CDIM  256
#define FDIM  512
#define LTOK  4096
#define NH    8
#define DHEAD 64
#define LN_EPS_C 1e-5f
#define BN_EPS_C 1e-5f
#define ATT_SCALE 0.125f     // 1/sqrt(64)
#define NCH   8              // l-chunks for weighted-sum partials
#define LCH   (LTOK/NCH)     // 512

// ---- local_kernel (tensor-core) geometry ----
#define TT    64             // tokens per CTA
#define KB    32             // k-chunk
#define ASTR  72             // As row stride (u32) -> bank-conflict-free frags
#define BSTR  520            // Bs row stride (u32) -> bank-conflict-free frags
#define CSTR  520            // Cs row stride (f32)
#define AB_U32  (KB*ASTR + KB*BSTR)          // 18944 u32 per stage buffer
#define CS_U32  (TT*CSTR)                    // 33280 floats (overlays both stage bufs)
#define SMEM_TOTAL_B ((2*AB_U32 + NH*FDIM + 4*FDIM) * 4)   // 176128 B

// ---------------- device scratch (no cudaMalloc allowed) ----------------
__device__ float  g_g[BATCH*FDIM];              // normalized global feature
__device__ float  g_u[BATCH*NH*FDIM];           // per-head folded query: u = q @ Wk_head
__device__ float  g_cb[BATCH*NH];               // q . bk per head
__device__ float  g_Wlt[CDIM*FDIM];             // Wl transposed (c-major)
__device__ float  g_sA[FDIM];                   // folded BN scale
__device__ float  g_tA[FDIM];                   // folded BN shift
__device__ __half g_x[(size_t)BATCH*LTOK*FDIM]; // normalized local tokens (128MB)
__device__ float  g_scores[BATCH*NH*LTOK];      // logits -> softmaxed in place
__device__ float  g_wpart[BATCH*NCH*NH*FDIM];   // partial attn-weighted sums

// ---------------- helpers ----------------
__device__ __forceinline__ float block_sum_512(float v, volatile float* red) {
    int t = threadIdx.x;
#pragma unroll
    for (int o = 16; o; o >>= 1) v += __shfl_xor_sync(0xffffffffu, v, o);
    if ((t & 31) == 0) red[t >> 5] = v;
    __syncthreads();
    float r = 0.f;
    if (t < 32) {
        r = (t < 16) ? red[t] : 0.f;
#pragma unroll
        for (int o = 8; o; o >>= 1) r += __shfl_xor_sync(0xffffffffu, r, o);
        if (t == 0) red[0] = r;
    }
    __syncthreads();
    r = red[0];
    __syncthreads();
    return r;
}

__device__ __forceinline__ void mma_tf32(float c[4], const unsigned a[4], const unsigned b[2]) {
    asm("mma.sync.aligned.m16n8k8.row.col.f32.tf32.tf32.f32 "
        "{%0,%1,%2,%3}, {%4,%5,%6,%7}, {%8,%9}, {%0,%1,%2,%3};"
        : "+f"(c[0]), "+f"(c[1]), "+f"(c[2]), "+f"(c[3])
        : "r"(a[0]), "r"(a[1]), "r"(a[2]), "r"(a[3]), "r"(b[0]), "r"(b[1]));
}

__device__ __forceinline__ void cp16(unsigned* dst_smem, const float* src) {
    unsigned d = (unsigned)__cvta_generic_to_shared(dst_smem);
    asm volatile("cp.async.cg.shared.global [%0], [%1], 16;\n" :: "r"(d), "l"(src));
}

// ---------------- kernel T: transpose Wl, fold BN ----------------
__global__ void prep_kernel(const float* __restrict__ Wl,
                            const float* __restrict__ bn_g, const float* __restrict__ bn_b,
                            const float* __restrict__ bn_m, const float* __restrict__ bn_v) {
    int c = blockIdx.x;          // 0..255
    int f = threadIdx.x;         // 0..511
    g_Wlt[c*FDIM + f] = Wl[f*CDIM + c];
    if (c == 0) {
        float s = bn_g[f] * rsqrtf(bn_v[f] + BN_EPS_C);
        g_sA[f] = s;
        g_tA[f] = bn_b[f] - bn_m[f]*s;
    }
}

// ---------------- kernel A: global branch + folded query ----------------
__global__ __launch_bounds__(512) void global_kernel(
    const float* __restrict__ gf, const float* __restrict__ Wg, const float* __restrict__ bg,
    const float* __restrict__ gn_g, const float* __restrict__ gn_b,
    const float* __restrict__ Wq, const float* __restrict__ bq,
    const float* __restrict__ Wk, const float* __restrict__ bk)
{
    __shared__ __align__(16) float sg[GDIM];
    __shared__ __align__(16) float s_g[FDIM];
    __shared__ __align__(16) float s_q[FDIM];
    __shared__ float red[16];
    int b = blockIdx.x, t = threadIdx.x;
    sg[t]       = gf[b*GDIM + t];
    sg[t + 512] = gf[b*GDIM + t + 512];
    __syncthreads();

    float acc = bg[t];
    {
        const float4* w4 = (const float4*)(Wg + (size_t)t*GDIM);
        const float4* x4 = (const float4*)sg;
#pragma unroll 8
        for (int k = 0; k < GDIM/4; k++) {
            float4 w = w4[k], x = x4[k];
            acc += w.x*x.x + w.y*x.y + w.z*x.z + w.w*x.w;
        }
    }
    float sum  = block_sum_512(acc, red);
    float sumq = block_sum_512(acc*acc, red);
    float mean = sum * (1.f/FDIM);
    float rstd = rsqrtf(sumq*(1.f/FDIM) - mean*mean + LN_EPS_C);
    float gval = (acc - mean)*rstd*gn_g[t] + gn_b[t];
    s_g[t] = gval;
    g_g[b*FDIM + t] = gval;
    __syncthreads();

    float qv = bq[t];
    {
        const float4* w4 = (const float4*)(Wq + (size_t)t*FDIM);
        const float4* x4 = (const float4*)s_g;
#pragma unroll 8
        for (int k = 0; k < FDIM/4; k++) {
            float4 w = w4[k], x = x4[k];
            qv += w.x*x.x + w.y*x.y + w.z*x.z + w.w*x.w;
        }
    }
    s_q[t] = qv;
    __syncthreads();

    int c = t;
#pragma unroll
    for (int h = 0; h < NH; h++) {
        float a = 0.f;
#pragma unroll 16
        for (int d = 0; d < DHEAD; d++)
            a += s_q[h*DHEAD + d] * __ldg(&Wk[(size_t)(h*DHEAD + d)*FDIM + c]);
        g_u[(b*NH + h)*FDIM + c] = a;
    }
    if (t < NH) {
        float a = 0.f;
#pragma unroll 16
        for (int d = 0; d < DHEAD; d++) a += s_q[t*DHEAD + d] * bk[t*DHEAD + d];
        g_cb[b*NH + t] = a;
    }
}

// ---------------- kernel B: conv1x1 GEMM on tensor cores + BN + ReLU + LN + scores ----------------
// cp.async double-buffered staging (no staging registers -> no spills).
// Raw fp32 bytes are fed to the tf32 MMA (hardware truncates low mantissa bits).
__global__ __launch_bounds__(512, 1) void local_kernel(
    const float* __restrict__ lf,
    const float* __restrict__ ln_g, const float* __restrict__ ln_b)
{
    extern __shared__ __align__(16) float smem[];
    unsigned* stage0 = (unsigned*)smem;          // [KB][ASTR] | [KB][BSTR]
    unsigned* stage1 = (unsigned*)smem + AB_U32;
    float*    Cs  = smem;                        // [TT][CSTR]  (epilogue, overlays stages)
    float*    u_s = smem + 2*AB_U32;             // [NH*FDIM]
    float*    prm = smem + 2*AB_U32 + NH*FDIM;   // sA | tA | ln_g | ln_b

    const int b  = blockIdx.y;
    const int l0 = blockIdx.x * TT;
    const int t  = threadIdx.x;
    const int wid  = t >> 5;
    const int lane = t & 31;
    const int warp_m = wid & 1;        // token half (32)
    const int warp_n = wid >> 1;       // feature group (64)
    const int qrow = lane >> 2;        // 0..7
    const int qcol = lane & 3;         // 0..3

    const float* lfb = lf + (size_t)b*CDIM*LTOK;

    // per-thread staging coordinates (fixed across chunks)
    const int sa_c = t >> 4;                 // 0..31
    const int sa_i = (t & 15) * 4;           // 0..60

    float acc[2][8][4];
#pragma unroll
    for (int mt = 0; mt < 2; mt++)
#pragma unroll
        for (int nt = 0; nt < 8; nt++)
#pragma unroll
            for (int i = 0; i < 4; i++) acc[mt][nt][i] = 0.f;

    // ---- issue helper: stage chunk (c0) into buffer base ----
    auto issue_chunk = [&](int c0, unsigned* base) {
        cp16(base + sa_c*ASTR + sa_i, &lfb[(size_t)(c0 + sa_c)*LTOK + l0 + sa_i]);
        unsigned* bb = base + KB*ASTR;
#pragma unroll
        for (int it = 0; it < 8; it++) {
            int idx = it*512 + t;
            int c2 = idx >> 7, fo = (idx & 127) * 4;
            cp16(bb + c2*BSTR + fo, &g_Wlt[(size_t)(c0 + c2)*FDIM + fo]);
        }
        asm volatile("cp.async.commit_group;\n");
    };

    // ---- prologue: two chunks in flight ----
    issue_chunk(0,  stage0);
    issue_chunk(KB, stage1);

    // ---- mainloop over K in chunks of KB ----
#pragma unroll 1
    for (int ci = 0; ci < CDIM/KB; ci++) {
        if (ci < CDIM/KB - 1) asm volatile("cp.async.wait_group 1;\n");
        else                  asm volatile("cp.async.wait_group 0;\n");
        __syncthreads();

        unsigned* As = (ci & 1) ? stage1 : stage0;
        unsigned* Bs = As + KB*ASTR;

#pragma unroll
        for (int ks = 0; ks < KB/8; ks++) {
            const int kk = ks * 8;
            unsigned afr[2][4], bfr[8][2];
#pragma unroll
            for (int mt = 0; mt < 2; mt++) {
                int row = warp_m*32 + mt*16 + qrow;
                afr[mt][0] = As[(kk + qcol    )*ASTR + row    ];
                afr[mt][1] = As[(kk + qcol    )*ASTR + row + 8];
                afr[mt][2] = As[(kk + qcol + 4)*ASTR + row    ];
                afr[mt][3] = As[(kk + qcol + 4)*ASTR + row + 8];
            }
#pragma unroll
            for (int nt = 0; nt < 8; nt++) {
                int f = warp_n*64 + nt*8 + qrow;
                bfr[nt][0] = Bs[(kk + qcol    )*BSTR + f];
                bfr[nt][1] = Bs[(kk + qcol + 4)*BSTR + f];
            }
#pragma unroll
            for (int mt = 0; mt < 2; mt++)
#pragma unroll
                for (int nt = 0; nt < 8; nt++)
                    mma_tf32(acc[mt][nt], afr[mt], bfr[nt]);
        }
        __syncthreads();   // all warps done reading this buffer

        if (ci + 2 < CDIM/KB) issue_chunk((ci + 2)*KB, As);
    }

    // ---- spill accumulators to Cs (mma layout -> [token][feature]) ----
#pragma unroll
    for (int mt = 0; mt < 2; mt++) {
#pragma unroll
        for (int nt = 0; nt < 8; nt++) {
            int row = warp_m*32 + mt*16 + qrow;
            int col = warp_n*64 + nt*8 + 2*qcol;
            *(float2*)&Cs[ row     *CSTR + col] = make_float2(acc[mt][nt][0], acc[mt][nt][1]);
            *(float2*)&Cs[(row + 8)*CSTR + col] = make_float2(acc[mt][nt][2], acc[mt][nt][3]);
        }
    }
    // load u and per-feature params (disjoint smem regions)
#pragma unroll
    for (int i = 0; i < 8; i++) u_s[t + 512*i] = g_u[(size_t)b*NH*FDIM + t + 512*i];
    prm[t]        = g_sA[t];
    prm[512 + t]  = g_tA[t];
    prm[1024 + t] = ln_g[t];
    prm[1536 + t] = ln_b[t];
    __syncthreads();

    // ---- per-token BN + ReLU + LN, fp16 stash (warp wid owns tokens wid*4..wid*4+3) ----
#pragma unroll
    for (int tok = 0; tok < 4; tok++) {
        int row = wid*4 + tok;
        float v[16];
        float s = 0.f, ss = 0.f;
#pragma unroll
        for (int j = 0; j < 16; j++) {
            int f = lane + 32*j;
            float r = fmaxf(fmaf(Cs[row*CSTR + f], prm[f], prm[512 + f]), 0.f);
            v[j] = r; s += r; ss += r*r;
        }
#pragma unroll
        for (int o = 16; o; o >>= 1) {
            s  += __shfl_xor_sync(0xffffffffu, s,  o);
            ss += __shfl_xor_sync(0xffffffffu, ss, o);
        }
        float mean = s * (1.f/FDIM);
        float rstd = rsqrtf(ss*(1.f/FDIM) - mean*mean + LN_EPS_C);
        __half* dst = g_x + ((size_t)(b*LTOK + l0 + row))*FDIM;
#pragma unroll
        for (int j = 0; j < 16; j++) {
            int f = lane + 32*j;
            float nx = fmaf((v[j] - mean)*rstd, prm[1024 + f], prm[1536 + f]);
            Cs[row*CSTR + f] = nx;
            dst[f] = __float2half_rn(nx);
        }
    }

    // ---- scores: p[tok][h] = x . u[h]  (1 LDS-u per 4 FMA) ----
    float p[4][8];
#pragma unroll
    for (int a = 0; a < 4; a++)
#pragma unroll
        for (int h = 0; h < 8; h++) p[a][h] = 0.f;
#pragma unroll
    for (int j = 0; j < 16; j++) {
        int f = lane + 32*j;
        float xv[4];
#pragma unroll
        for (int a = 0; a < 4; a++) xv[a] = Cs[(wid*4 + a)*CSTR + f];
#pragma unroll
        for (int h = 0; h < 8; h++) {
            float uv = u_s[h*FDIM + f];
#pragma unroll
            for (int a = 0; a < 4; a++) p[a][h] = fmaf(xv[a], uv, p[a][h]);
        }
    }
#pragma unroll
    for (int a = 0; a < 4; a++)
#pragma unroll
        for (int h = 0; h < 8; h++)
#pragma unroll
            for (int o = 16; o; o >>= 1)
                p[a][h] += __shfl_xor_sync(0xffffffffu, p[a][h], o);

    {
        int hh = lane & 7, tk = lane >> 3;
        float v = 0.f;
#pragma unroll
        for (int a = 0; a < 4; a++)
#pragma unroll
            for (int h = 0; h < 8; h++)
                if (a == tk && h == hh) v = p[a][h];
        g_scores[(size_t)(b*NH + hh)*LTOK + l0 + wid*4 + tk] =
            (v + g_cb[b*NH + hh]) * ATT_SCALE;
    }
}

// ---------------- kernel C: softmax over L per (b,h) ----------------
__global__ __launch_bounds__(256) void softmax_kernel() {
    int r = blockIdx.x;                      // b*8+h
    float* row = g_scores + (size_t)r*LTOK;
    __shared__ float red[8];
    int t = threadIdx.x;
    float v[16];
    float mx = -1e30f;
#pragma unroll
    for (int i = 0; i < 16; i++) { v[i] = row[t + 256*i]; mx = fmaxf(mx, v[i]); }
#pragma unroll
    for (int o = 16; o; o >>= 1) mx = fmaxf(mx, __shfl_xor_sync(0xffffffffu, mx, o));
    if ((t & 31) == 0) red[t >> 5] = mx;
    __syncthreads();
    if (t < 32) {
        float m = (t < 8) ? red[t] : -1e30f;
#pragma unroll
        for (int o = 4; o; o >>= 1) m = fmaxf(m, __shfl_xor_sync(0xffffffffu, m, o));
        if (t == 0) red[0] = m;
    }
    __syncthreads();
    mx = red[0];
    __syncthreads();
    float s = 0.f;
#pragma unroll
    for (int i = 0; i < 16; i++) { v[i] = __expf(v[i] - mx); s += v[i]; }
#pragma unroll
    for (int o = 16; o; o >>= 1) s += __shfl_xor_sync(0xffffffffu, s, o);
    if ((t & 31) == 0) red[t >> 5] = s;
    __syncthreads();
    if (t < 32) {
        float m = (t < 8) ? red[t] : 0.f;
#pragma unroll
        for (int o = 4; o; o >>= 1) m += __shfl_xor_sync(0xffffffffu, m, o);
        if (t == 0) red[0] = m;
    }
    __syncthreads();
    float inv = 1.f / red[0];
#pragma unroll
    for (int i = 0; i < 16; i++) row[t + 256*i] = v[i] * inv;
}

// ---------------- kernel D: w_part[b,ch,h,c] = sum_l attn * x ----------------
__global__ __launch_bounds__(256) void wsum_kernel() {
    int b = blockIdx.y, ch = blockIdx.x;
    int l0 = ch * LCH;
    __shared__ float at[NH][LCH];   // 16KB
    int t = threadIdx.x;
    for (int i = t; i < NH*LCH; i += 256) {
        int h = i >> 9, l = i & 511;
        at[h][l] = g_scores[(size_t)(b*NH + h)*LTOK + l0 + l];
    }
    __syncthreads();
    float acc[16];
#pragma unroll
    for (int i = 0; i < 16; i++) acc[i] = 0.f;
    const __half2* xp = (const __half2*)g_x + (size_t)(b*LTOK + l0)*(FDIM/2) + t;
#pragma unroll 4
    for (int l = 0; l < LCH; l++) {
        float2 xv = __half22float2(xp[(size_t)l*(FDIM/2)]);
#pragma unroll
        for (int h = 0; h < NH; h++) {
            float a = at[h][l];
            acc[2*h]   = fmaf(a, xv.x, acc[2*h]);
            acc[2*h+1] = fmaf(a, xv.y, acc[2*h+1]);
        }
    }
    float* wp = g_wpart + (size_t)((b*NCH + ch)*NH)*FDIM;
#pragma unroll
    for (int h = 0; h < NH; h++)
        *(float2*)&wp[h*FDIM + 2*t] = make_float2(acc[2*h], acc[2*h+1]);
}

// ---------------- kernel E: o/attended/gate/MLP/LN ----------------
__global__ __launch_bounds__(512) void fuse_kernel(
    const float* __restrict__ Wv, const float* __restrict__ bv,
    const float* __restrict__ Wo, const float* __restrict__ bo,
    const float* __restrict__ Wgate, const float* __restrict__ bgate,
    const float* __restrict__ We1, const float* __restrict__ be1,
    const float* __restrict__ We2, const float* __restrict__ be2,
    const float* __restrict__ eln_g, const float* __restrict__ eln_b,
    float* __restrict__ out)
{
    __shared__ __align__(16) float w_s[NH*FDIM];   // 16KB
    __shared__ __align__(16) float o_s[FDIM];
    __shared__ __align__(16) float att_s[FDIM];
    __shared__ __align__(16) float gs[FDIM];
    __shared__ __align__(16) float fu[FDIM];
    __shared__ __align__(16) float h1[2*FDIM];
    __shared__ float red[16];
    int b = blockIdx.x, t = threadIdx.x;

    for (int i = t; i < NH*FDIM; i += 512) {
        float s = 0.f;
#pragma unroll
        for (int ch = 0; ch < NCH; ch++)
            s += g_wpart[(size_t)((b*NCH + ch)*NH)*FDIM + i];
        w_s[i] = s;
    }
    gs[t] = g_g[b*FDIM + t];
    __syncthreads();

    {
        int h = t >> 6;
        float a = bv[t];
        const float4* wr = (const float4*)(Wv + (size_t)t*FDIM);
        const float4* ws = (const float4*)(w_s + h*FDIM);
#pragma unroll 8
        for (int k = 0; k < FDIM/4; k++) {
            float4 w = wr[k], x = ws[k];
            a += w.x*x.x + w.y*x.y + w.z*x.z + w.w*x.w;
        }
        o_s[t] = a;
    }
    __syncthreads();

    {
        float a = bo[t];
        const float4* wr = (const float4*)(Wo + (size_t)t*FDIM);
        const float4* xs = (const float4*)o_s;
#pragma unroll 8
        for (int k = 0; k < FDIM/4; k++) {
            float4 w = wr[k], x = xs[k];
            a += w.x*x.x + w.y*x.y + w.z*x.z + w.w*x.w;
        }
        att_s[t] = a;
    }
    __syncthreads();

    {
        float z = bgate[t];
        const float4* wr = (const float4*)(Wgate + (size_t)t*2*FDIM);
        const float4* xg = (const float4*)gs;
        const float4* xa = (const float4*)att_s;
#pragma unroll 8
        for (int k = 0; k < FDIM/4; k++) {
            float4 w = wr[k], x = xg[k];
            z += w.x*x.x + w.y*x.y + w.z*x.z + w.w*x.w;
        }
#pragma unroll 8
        for (int k = 0; k < FDIM/4; k++) {
            float4 w = wr[FDIM/4 + k], x = xa[k];
            z += w.x*x.x + w.y*x.y + w.z*x.z + w.w*x.w;
        }
        float gate = 1.f / (1.f + expf(-z));
        fu[t] = gate*gs[t] + (1.f - gate)*att_s[t];
    }
    __syncthreads();

#pragma unroll
    for (int rr = 0; rr < 2; rr++) {
        int j = t + 512*rr;
        float a = be1[j];
        const float4* wr = (const float4*)(We1 + (size_t)j*FDIM);
        const float4* xs = (const float4*)fu;
#pragma unroll 8
        for (int k = 0; k < FDIM/4; k++) {
            float4 w = wr[k], x = xs[k];
            a += w.x*x.x + w.y*x.y + w.z*x.z + w.w*x.w;
        }
        h1[j] = 0.5f * a * (1.f + erff(a * 0.70710678118654752f));
    }
    __syncthreads();

    float v = be2[t];
    {
        const float4* wr = (const float4*)(We2 + (size_t)t*2*FDIM);
        const float4* xs = (const float4*)h1;
#pragma unroll 8
        for (int k = 0; k < 2*FDIM/4; k++) {
            float4 w = wr[k], x = xs[k];
            v += w.x*x.x + w.y*x.y + w.z*x.z + w.w*x.w;
        }
    }
    float sum  = block_sum_512(v, red);
    float sumq = block_sum_512(v*v, red);
    float mean = sum * (1.f/FDIM);
    float rstd = rsqrtf(sumq*(1.f/FDIM) - mean*mean + LN_EPS_C);
    out[b*FDIM + t] = (v - mean)*rstd*eln_g[t] + eln_b[t];
}

// ---------------- launch ----------------
extern "C" void kernel_launch(void* const* d_in, const int* in_sizes, int n_in,
                              void* d_out, int out_size) {
    const float* global_feat = (const float*)d_in[0];
    const float* local_feat  = (const float*)d_in[1];
    const float* Wg    = (const float*)d_in[2];
    const float* bg    = (const float*)d_in[3];
    const float* gn_g  = (const float*)d_in[4];
    const float* gn_b  = (const float*)d_in[5];
    const float* Wl    = (const float*)d_in[6];
    const float* bn_g  = (const float*)d_in[7];
    const float* bn_b  = (const float*)d_in[8];
    const float* bn_m  = (const float*)d_in[9];
    const float* bn_v  = (const float*)d_in[10];
    const float* ln_g  = (const float*)d_in[11];
    const float* ln_b  = (const float*)d_in[12];
    const float* Wq    = (const float*)d_in[13];
    const float* bq    = (const float*)d_in[14];
    const float* Wk    = (const float*)d_in[15];
    const float* bk    = (const float*)d_in[16];
    const float* Wv    = (const float*)d_in[17];
    const float* bv    = (const float*)d_in[18];
    const float* Wo    = (const float*)d_in[19];
    const float* bo    = (const float*)d_in[20];
    const float* Wgate = (const float*)d_in[21];
    const float* bgate = (const float*)d_in[22];
    const float* We1   = (const float*)d_in[23];
    const float* be1   = (const float*)d_in[24];
    const float* We2   = (const float*)d_in[25];
    const float* be2   = (const float*)d_in[26];
    const float* eln_g = (const float*)d_in[27];
    const float* eln_b = (const float*)d_in[28];
    float* out = (float*)d_out;

    // Unconditional (no static guards); not stream-ordered, capture-safe.
    (void)cudaFuncSetAttribute(local_kernel,
                               cudaFuncAttributeMaxDynamicSharedMemorySize, SMEM_TOTAL_B);

    prep_kernel<<<CDIM, FDIM>>>(Wl, bn_g, bn_b, bn_m, bn_v);
    global_kernel<<<BATCH, 512>>>(global_feat, Wg, bg, gn_g, gn_b, Wq, bq, Wk, bk);
    local_kernel<<<dim3(LTOK/TT, BATCH), 512, SMEM_TOTAL_B>>>(local_feat, ln_g, ln_b);
    softmax_kernel<<<BATCH*NH, 256>>>();
    wsum_kernel<<<dim3(NCH, BATCH), 256>>>();
    fuse_kernel<<<BATCH, 512>>>(Wv, bv, Wo, bo, Wgate, bgate,
                                We1, be1, We2, be2, eln_g, eln_b, out);
}

// round 11
// speedup vs baseline: 1.9570x; 1.0456x over previous
#include <cuda_runtime.h>
#include <cuda_fp16.h>
#include <math.h>

// ---------------- problem constants ----------------
#define BATCH 32
#define GDIM  1024
#define CDIM  256
#define FDIM  512
#define LTOK  4096
#define NH    8
#define DHEAD 64
#define LN_EPS_C 1e-5f
#define BN_EPS_C 1e-5f
#define ATT_SCALE 0.125f     // 1/sqrt(64)
#define NCH   8              // l-chunks for weighted-sum partials
#define LCH   (LTOK/NCH)     // 512

// ---- local_kernel (fp16 tensor-core) geometry ----
#define TT    64             // tokens per CTA
#define KB    32             // k-chunk
#define ASH   72             // A stage row stride (halves): banks 4k+c, conflict-free ldsm
#define BSH   40             // B stage row stride (halves): banks 20r mod 32 distinct
#define A_HALVES   (KB*ASH)                 // 2304
#define STG_HALVES (A_HALVES + FDIM*BSH)    // 2304 + 20480 = 22784 halves = 45568 B
#define CSTR  520            // Cs row stride (f32)
#define CS_U32  (TT*CSTR)                   // 33280 floats (overlays both stage bufs)
#define SMEM_TOTAL_B ((CS_U32 + NH*FDIM + 4*FDIM) * 4)   // 157696 B

// ---------------- device scratch (no cudaMalloc allowed) ----------------
__device__ float  g_g[BATCH*FDIM];              // normalized global feature
__device__ float  g_u[BATCH*NH*FDIM];           // per-head folded query: u = q @ Wk_head
__device__ float  g_cb[BATCH*NH];               // q . bk per head
__device__ __align__(16) __half g_Wl_h[FDIM*CDIM];            // Wl fp16, natural [f][c]
__device__ __align__(16) __half g_lf_h[(size_t)BATCH*CDIM*LTOK]; // local_feat fp16 [b][c][l]
__device__ float  g_sA[FDIM];                   // folded BN scale
__device__ float  g_tA[FDIM];                   // folded BN shift
__device__ __half g_x[(size_t)BATCH*LTOK*FDIM]; // normalized local tokens (128MB)
__device__ float  g_scores[BATCH*NH*LTOK];      // logits -> softmaxed in place
__device__ float  g_wpart[BATCH*NCH*NH*FDIM];   // partial attn-weighted sums

// ---------------- helpers ----------------
__device__ __forceinline__ float block_sum_512(float v, volatile float* red) {
    int t = threadIdx.x;
#pragma unroll
    for (int o = 16; o; o >>= 1) v += __shfl_xor_sync(0xffffffffu, v, o);
    if ((t & 31) == 0) red[t >> 5] = v;
    __syncthreads();
    float r = 0.f;
    if (t < 32) {
        r = (t < 16) ? red[t] : 0.f;
#pragma unroll
        for (int o = 8; o; o >>= 1) r += __shfl_xor_sync(0xffffffffu, r, o);
        if (t == 0) red[0] = r;
    }
    __syncthreads();
    r = red[0];
    __syncthreads();
    return r;
}

__device__ __forceinline__ void mma_f16(float c[4], const unsigned a[4], unsigned b0, unsigned b1) {
    asm("mma.sync.aligned.m16n8k16.row.col.f32.f16.f16.f32 "
        "{%0,%1,%2,%3}, {%4,%5,%6,%7}, {%8,%9}, {%0,%1,%2,%3};"
        : "+f"(c[0]), "+f"(c[1]), "+f"(c[2]), "+f"(c[3])
        : "r"(a[0]), "r"(a[1]), "r"(a[2]), "r"(a[3]), "r"(b0), "r"(b1));
}

__device__ __forceinline__ void ldsm_x4(unsigned r[4], unsigned addr) {
    asm volatile("ldmatrix.sync.aligned.m8n8.x4.shared.b16 {%0,%1,%2,%3}, [%4];"
        : "=r"(r[0]), "=r"(r[1]), "=r"(r[2]), "=r"(r[3]) : "r"(addr));
}
__device__ __forceinline__ void ldsm_x4_t(unsigned r[4], unsigned addr) {
    asm volatile("ldmatrix.sync.aligned.m8n8.x4.trans.shared.b16 {%0,%1,%2,%3}, [%4];"
        : "=r"(r[0]), "=r"(r[1]), "=r"(r[2]), "=r"(r[3]) : "r"(addr));
}

__device__ __forceinline__ void cp16(void* dst_smem, const void* src) {
    unsigned d = (unsigned)__cvta_generic_to_shared(dst_smem);
    asm volatile("cp.async.cg.shared.global [%0], [%1], 16;\n" :: "r"(d), "l"(src));
}

// ---------------- kernel T: Wl -> fp16, fold BN ----------------
__global__ void prep_kernel(const float* __restrict__ Wl,
                            const float* __restrict__ bn_g, const float* __restrict__ bn_b,
                            const float* __restrict__ bn_m, const float* __restrict__ bn_v) {
    int f = blockIdx.x;          // 0..511
    int c = threadIdx.x;         // 0..255
    g_Wl_h[f*CDIM + c] = __float2half_rn(Wl[f*CDIM + c]);
    if (c == 0) {
        float s = bn_g[f] * rsqrtf(bn_v[f] + BN_EPS_C);
        g_sA[f] = s;
        g_tA[f] = bn_b[f] - bn_m[f]*s;
    }
}

// ---------------- kernel V: local_feat -> fp16 ----------------
__global__ __launch_bounds__(256) void cvt_kernel(const float* __restrict__ lf) {
    const size_t total4 = (size_t)BATCH*CDIM*LTOK/4;
    size_t stride = (size_t)gridDim.x*blockDim.x;
    for (size_t i = blockIdx.x*(size_t)blockDim.x + threadIdx.x; i < total4; i += stride) {
        float4 v = *(const float4*)(lf + i*4);
        __half2* d = (__half2*)(g_lf_h + i*4);
        d[0] = __floats2half2_rn(v.x, v.y);
        d[1] = __floats2half2_rn(v.z, v.w);
    }
}

// ---------------- kernel A: global branch + folded query ----------------
__global__ __launch_bounds__(512) void global_kernel(
    const float* __restrict__ gf, const float* __restrict__ Wg, const float* __restrict__ bg,
    const float* __restrict__ gn_g, const float* __restrict__ gn_b,
    const float* __restrict__ Wq, const float* __restrict__ bq,
    const float* __restrict__ Wk, const float* __restrict__ bk)
{
    __shared__ __align__(16) float sg[GDIM];
    __shared__ __align__(16) float s_g[FDIM];
    __shared__ __align__(16) float s_q[FDIM];
    __shared__ float red[16];
    int b = blockIdx.x, t = threadIdx.x;
    sg[t]       = gf[b*GDIM + t];
    sg[t + 512] = gf[b*GDIM + t + 512];
    __syncthreads();

    float acc = bg[t];
    {
        const float4* w4 = (const float4*)(Wg + (size_t)t*GDIM);
        const float4* x4 = (const float4*)sg;
#pragma unroll 8
        for (int k = 0; k < GDIM/4; k++) {
            float4 w = w4[k], x = x4[k];
            acc += w.x*x.x + w.y*x.y + w.z*x.z + w.w*x.w;
        }
    }
    float sum  = block_sum_512(acc, red);
    float sumq = block_sum_512(acc*acc, red);
    float mean = sum * (1.f/FDIM);
    float rstd = rsqrtf(sumq*(1.f/FDIM) - mean*mean + LN_EPS_C);
    float gval = (acc - mean)*rstd*gn_g[t] + gn_b[t];
    s_g[t] = gval;
    g_g[b*FDIM + t] = gval;
    __syncthreads();

    float qv = bq[t];
    {
        const float4* w4 = (const float4*)(Wq + (size_t)t*FDIM);
        const float4* x4 = (const float4*)s_g;
#pragma unroll 8
        for (int k = 0; k < FDIM/4; k++) {
            float4 w = w4[k], x = x4[k];
            qv += w.x*x.x + w.y*x.y + w.z*x.z + w.w*x.w;
        }
    }
    s_q[t] = qv;
    __syncthreads();

    int c = t;
#pragma unroll
    for (int h = 0; h < NH; h++) {
        float a = 0.f;
#pragma unroll 16
        for (int d = 0; d < DHEAD; d++)
            a += s_q[h*DHEAD + d] * __ldg(&Wk[(size_t)(h*DHEAD + d)*FDIM + c]);
        g_u[(b*NH + h)*FDIM + c] = a;
    }
    if (t < NH) {
        float a = 0.f;
#pragma unroll 16
        for (int d = 0; d < DHEAD; d++) a += s_q[t*DHEAD + d] * bk[t*DHEAD + d];
        g_cb[b*NH + t] = a;
    }
}

// ---------------- kernel B: conv1x1 GEMM (fp16 mma.m16n8k16 + ldmatrix) + BN + ReLU + LN + scores ----------------
// A staged [k][m] fp16 (gmem-native) -> ldmatrix.x4.trans
// B staged [f][c] fp16 (Wl-native)   -> ldmatrix.x4
// cp.async double-buffered; fp32 accumulate; epilogue identical to tf32 version.
__global__ __launch_bounds__(512, 1) void local_kernel(
    const float* __restrict__ ln_g, const float* __restrict__ ln_b)
{
    extern __shared__ __align__(16) float smem[];
    __half* stg0 = (__half*)smem;               // A[KB][ASH] | B[FDIM][BSH]
    __half* stg1 = stg0 + STG_HALVES;
    float*  Cs   = smem;                        // [TT][CSTR] (epilogue overlay)
    float*  u_s  = smem + CS_U32;               // [NH*FDIM]
    float*  prm  = smem + CS_U32 + NH*FDIM;     // sA | tA | ln_g | ln_b

    const int b  = blockIdx.y;
    const int l0 = blockIdx.x * TT;
    const int t  = threadIdx.x;
    const int wid  = t >> 5;
    const int lane = t & 31;
    const int warp_m = wid & 1;        // token half (32)
    const int warp_n = wid >> 1;       // feature group (64)
    const int qrow = lane >> 2;        // 0..7
    const int qcol = lane & 3;         // 0..3

    // ldmatrix per-lane base offsets (halves)
    // A (trans, [k][m]): group g=lane>>3: g&1 -> m+8, g>>1 -> k+8
    const int a_off = ((lane & 7) + ((lane >> 4) & 1) * 8) * ASH + ((lane >> 3) & 1) * 8;
    // B (no-trans, [f][c]): g&1 -> n+8, g>>1 -> k+8
    const int b_off = ((lane & 7) + ((lane >> 3) & 1) * 8) * BSH + ((lane >> 4) & 1) * 8;

    float acc[2][8][4];
#pragma unroll
    for (int mt = 0; mt < 2; mt++)
#pragma unroll
        for (int nt = 0; nt < 8; nt++)
#pragma unroll
            for (int i = 0; i < 4; i++) acc[mt][nt][i] = 0.f;

    // ---- stage chunk c0 into buffer ----
    auto issue_chunk = [&](int c0, __half* base) {
        if (t < 256) {   // A: 32 rows x 128B
            int row = t >> 3, ch = t & 7;
            cp16(base + row*ASH + ch*8,
                 g_lf_h + ((size_t)b*CDIM + c0 + row)*LTOK + l0 + ch*8);
        }
        __half* bb = base + A_HALVES;
#pragma unroll
        for (int it = 0; it < 4; it++) {   // B: 512 rows x 64B
            int idx = it*512 + t;
            int row = idx >> 2, ch = idx & 3;
            cp16(bb + row*BSH + ch*8, g_Wl_h + row*CDIM + c0 + ch*8);
        }
        asm volatile("cp.async.commit_group;\n");
    };

    issue_chunk(0,  stg0);
    issue_chunk(KB, stg1);

#pragma unroll 1
    for (int ci = 0; ci < CDIM/KB; ci++) {
        if (ci < CDIM/KB - 1) asm volatile("cp.async.wait_group 1;\n");
        else                  asm volatile("cp.async.wait_group 0;\n");
        __syncthreads();

        __half* base = (ci & 1) ? stg1 : stg0;
        unsigned a_smem = (unsigned)__cvta_generic_to_shared(base);
        unsigned b_smem = (unsigned)__cvta_generic_to_shared(base + A_HALVES);

#pragma unroll
        for (int kt = 0; kt < 2; kt++) {
            const int kk = kt * 16;
            unsigned afr[2][4], bfr[4][4];
#pragma unroll
            for (int mt = 0; mt < 2; mt++) {
                int m0 = warp_m*32 + mt*16;
                ldsm_x4_t(afr[mt], a_smem + (a_off + kk*ASH + m0) * 2);
            }
#pragma unroll
            for (int np = 0; np < 4; np++) {
                int n0 = warp_n*64 + np*16;
                ldsm_x4(bfr[np], b_smem + (b_off + n0*BSH + kk) * 2);
            }
#pragma unroll
            for (int mt = 0; mt < 2; mt++)
#pragma unroll
                for (int nt = 0; nt < 8; nt++) {
                    int np = nt >> 1, odd = nt & 1;
                    mma_f16(acc[mt][nt], afr[mt], bfr[np][odd], bfr[np][2 + odd]);
                }
        }
        __syncthreads();   // all warps done reading this buffer

        if (ci + 2 < CDIM/KB) issue_chunk((ci + 2)*KB, base);
    }

    // ---- spill accumulators to Cs (mma layout -> [token][feature]) ----
#pragma unroll
    for (int mt = 0; mt < 2; mt++) {
#pragma unroll
        for (int nt = 0; nt < 8; nt++) {
            int row = warp_m*32 + mt*16 + qrow;
            int col = warp_n*64 + nt*8 + 2*qcol;
            *(float2*)&Cs[ row     *CSTR + col] = make_float2(acc[mt][nt][0], acc[mt][nt][1]);
            *(float2*)&Cs[(row + 8)*CSTR + col] = make_float2(acc[mt][nt][2], acc[mt][nt][3]);
        }
    }
    // load u and per-feature params (disjoint smem regions)
#pragma unroll
    for (int i = 0; i < 8; i++) u_s[t + 512*i] = g_u[(size_t)b*NH*FDIM + t + 512*i];
    prm[t]        = g_sA[t];
    prm[512 + t]  = g_tA[t];
    prm[1024 + t] = ln_g[t];
    prm[1536 + t] = ln_b[t];
    __syncthreads();

    // ---- per-token BN + ReLU + LN, fp16 stash (warp wid owns tokens wid*4..wid*4+3) ----
#pragma unroll
    for (int tok = 0; tok < 4; tok++) {
        int row = wid*4 + tok;
        float v[16];
        float s = 0.f, ss = 0.f;
#pragma unroll
        for (int j = 0; j < 16; j++) {
            int f = lane + 32*j;
            float r = fmaxf(fmaf(Cs[row*CSTR + f], prm[f], prm[512 + f]), 0.f);
            v[j] = r; s += r; ss += r*r;
        }
#pragma unroll
        for (int o = 16; o; o >>= 1) {
            s  += __shfl_xor_sync(0xffffffffu, s,  o);
            ss += __shfl_xor_sync(0xffffffffu, ss, o);
        }
        float mean = s * (1.f/FDIM);
        float rstd = rsqrtf(ss*(1.f/FDIM) - mean*mean + LN_EPS_C);
        __half* dst = g_x + ((size_t)(b*LTOK + l0 + row))*FDIM;
#pragma unroll
        for (int j = 0; j < 16; j++) {
            int f = lane + 32*j;
            float nx = fmaf((v[j] - mean)*rstd, prm[1024 + f], prm[1536 + f]);
            Cs[row*CSTR + f] = nx;
            dst[f] = __float2half_rn(nx);
        }
    }

    // ---- scores: p[tok][h] = x . u[h]  (1 LDS-u per 4 FMA) ----
    float p[4][8];
#pragma unroll
    for (int a = 0; a < 4; a++)
#pragma unroll
        for (int h = 0; h < 8; h++) p[a][h] = 0.f;
#pragma unroll
    for (int j = 0; j < 16; j++) {
        int f = lane + 32*j;
        float xv[4];
#pragma unroll
        for (int a = 0; a < 4; a++) xv[a] = Cs[(wid*4 + a)*CSTR + f];
#pragma unroll
        for (int h = 0; h < 8; h++) {
            float uv = u_s[h*FDIM + f];
#pragma unroll
            for (int a = 0; a < 4; a++) p[a][h] = fmaf(xv[a], uv, p[a][h]);
        }
    }
#pragma unroll
    for (int a = 0; a < 4; a++)
#pragma unroll
        for (int h = 0; h < 8; h++)
#pragma unroll
            for (int o = 16; o; o >>= 1)
                p[a][h] += __shfl_xor_sync(0xffffffffu, p[a][h], o);

    {
        int hh = lane & 7, tk = lane >> 3;
        float v = 0.f;
#pragma unroll
        for (int a = 0; a < 4; a++)
#pragma unroll
            for (int h = 0; h < 8; h++)
                if (a == tk && h == hh) v = p[a][h];
        g_scores[(size_t)(b*NH + hh)*LTOK + l0 + wid*4 + tk] =
            (v + g_cb[b*NH + hh]) * ATT_SCALE;
    }
}

// ---------------- kernel C: softmax over L per (b,h) ----------------
__global__ __launch_bounds__(256) void softmax_kernel() {
    int r = blockIdx.x;                      // b*8+h
    float* row = g_scores + (size_t)r*LTOK;
    __shared__ float red[8];
    int t = threadIdx.x;
    float v[16];
    float mx = -1e30f;
#pragma unroll
    for (int i = 0; i < 16; i++) { v[i] = row[t + 256*i]; mx = fmaxf(mx, v[i]); }
#pragma unroll
    for (int o = 16; o; o >>= 1) mx = fmaxf(mx, __shfl_xor_sync(0xffffffffu, mx, o));
    if ((t & 31) == 0) red[t >> 5] = mx;
    __syncthreads();
    if (t < 32) {
        float m = (t < 8) ? red[t] : -1e30f;
#pragma unroll
        for (int o = 4; o; o >>= 1) m = fmaxf(m, __shfl_xor_sync(0xffffffffu, m, o));
        if (t == 0) red[0] = m;
    }
    __syncthreads();
    mx = red[0];
    __syncthreads();
    float s = 0.f;
#pragma unroll
    for (int i = 0; i < 16; i++) { v[i] = __expf(v[i] - mx); s += v[i]; }
#pragma unroll
    for (int o = 16; o; o >>= 1) s += __shfl_xor_sync(0xffffffffu, s, o);
    if ((t & 31) == 0) red[t >> 5] = s;
    __syncthreads();
    if (t < 32) {
        float m = (t < 8) ? red[t] : 0.f;
#pragma unroll
        for (int o = 4; o; o >>= 1) m += __shfl_xor_sync(0xffffffffu, m, o);
        if (t == 0) red[0] = m;
    }
    __syncthreads();
    float inv = 1.f / red[0];
#pragma unroll
    for (int i = 0; i < 16; i++) row[t + 256*i] = v[i] * inv;
}

// ---------------- kernel D: w_part[b,ch,h,c] = sum_l attn * x ----------------
__global__ __launch_bounds__(256) void wsum_kernel() {
    int b = blockIdx.y, ch = blockIdx.x;
    int l0 = ch * LCH;
    __shared__ float at[NH][LCH];   // 16KB
    int t = threadIdx.x;
    for (int i = t; i < NH*LCH; i += 256) {
        int h = i >> 9, l = i & 511;
        at[h][l] = g_scores[(size_t)(b*NH + h)*LTOK + l0 + l];
    }
    __syncthreads();
    float acc[16];
#pragma unroll
    for (int i = 0; i < 16; i++) acc[i] = 0.f;
    const __half2* xp = (const __half2*)g_x + (size_t)(b*LTOK + l0)*(FDIM/2) + t;
#pragma unroll 4
    for (int l = 0; l < LCH; l++) {
        float2 xv = __half22float2(xp[(size_t)l*(FDIM/2)]);
#pragma unroll
        for (int h = 0; h < NH; h++) {
            float a = at[h][l];
            acc[2*h]   = fmaf(a, xv.x, acc[2*h]);
            acc[2*h+1] = fmaf(a, xv.y, acc[2*h+1]);
        }
    }
    float* wp = g_wpart + (size_t)((b*NCH + ch)*NH)*FDIM;
#pragma unroll
    for (int h = 0; h < NH; h++)
        *(float2*)&wp[h*FDIM + 2*t] = make_float2(acc[2*h], acc[2*h+1]);
}

// ---------------- kernel E: o/attended/gate/MLP/LN ----------------
__global__ __launch_bounds__(512) void fuse_kernel(
    const float* __restrict__ Wv, const float* __restrict__ bv,
    const float* __restrict__ Wo, const float* __restrict__ bo,
    const float* __restrict__ Wgate, const float* __restrict__ bgate,
    const float* __restrict__ We1, const float* __restrict__ be1,
    const float* __restrict__ We2, const float* __restrict__ be2,
    const float* __restrict__ eln_g, const float* __restrict__ eln_b,
    float* __restrict__ out)
{
    __shared__ __align__(16) float w_s[NH*FDIM];   // 16KB
    __shared__ __align__(16) float o_s[FDIM];
    __shared__ __align__(16) float att_s[FDIM];
    __shared__ __align__(16) float gs[FDIM];
    __shared__ __align__(16) float fu[FDIM];
    __shared__ __align__(16) float h1[2*FDIM];
    __shared__ float red[16];
    int b = blockIdx.x, t = threadIdx.x;

    for (int i = t; i < NH*FDIM; i += 512) {
        float s = 0.f;
#pragma unroll
        for (int ch = 0; ch < NCH; ch++)
            s += g_wpart[(size_t)((b*NCH + ch)*NH)*FDIM + i];
        w_s[i] = s;
    }
    gs[t] = g_g[b*FDIM + t];
    __syncthreads();

    {
        int h = t >> 6;
        float a = bv[t];
        const float4* wr = (const float4*)(Wv + (size_t)t*FDIM);
        const float4* ws = (const float4*)(w_s + h*FDIM);
#pragma unroll 8
        for (int k = 0; k < FDIM/4; k++) {
            float4 w = wr[k], x = ws[k];
            a += w.x*x.x + w.y*x.y + w.z*x.z + w.w*x.w;
        }
        o_s[t] = a;
    }
    __syncthreads();

    {
        float a = bo[t];
        const float4* wr = (const float4*)(Wo + (size_t)t*FDIM);
        const float4* xs = (const float4*)o_s;
#pragma unroll 8
        for (int k = 0; k < FDIM/4; k++) {
            float4 w = wr[k], x = xs[k];
            a += w.x*x.x + w.y*x.y + w.z*x.z + w.w*x.w;
        }
        att_s[t] = a;
    }
    __syncthreads();

    {
        float z = bgate[t];
        const float4* wr = (const float4*)(Wgate + (size_t)t*2*FDIM);
        const float4* xg = (const float4*)gs;
        const float4* xa = (const float4*)att_s;
#pragma unroll 8
        for (int k = 0; k < FDIM/4; k++) {
            float4 w = wr[k], x = xg[k];
            z += w.x*x.x + w.y*x.y + w.z*x.z + w.w*x.w;
        }
#pragma unroll 8
        for (int k = 0; k < FDIM/4; k++) {
            float4 w = wr[FDIM/4 + k], x = xa[k];
            z += w.x*x.x + w.y*x.y + w.z*x.z + w.w*x.w;
        }
        float gate = 1.f / (1.f + expf(-z));
        fu[t] = gate*gs[t] + (1.f - gate)*att_s[t];
    }
    __syncthreads();

#pragma unroll
    for (int rr = 0; rr < 2; rr++) {
        int j = t + 512*rr;
        float a = be1[j];
        const float4* wr = (const float4*)(We1 + (size_t)j*FDIM);
        const float4* xs = (const float4*)fu;
#pragma unroll 8
        for (int k = 0; k < FDIM/4; k++) {
            float4 w = wr[k], x = xs[k];
            a += w.x*x.x + w.y*x.y + w.z*x.z + w.w*x.w;
        }
        h1[j] = 0.5f * a * (1.f + erff(a * 0.70710678118654752f));
    }
    __syncthreads();

    float v = be2[t];
    {
        const float4* wr = (const float4*)(We2 + (size_t)t*2*FDIM);
        const float4* xs = (const float4*)h1;
#pragma unroll 8
        for (int k = 0; k < 2*FDIM/4; k++) {
            float4 w = wr[k], x = xs[k];
            v += w.x*x.x + w.y*x.y + w.z*x.z + w.w*x.w;
        }
    }
    float sum  = block_sum_512(v, red);
    float sumq = block_sum_512(v*v, red);
    float mean = sum * (1.f/FDIM);
    float rstd = rsqrtf(sumq*(1.f/FDIM) - mean*mean + LN_EPS_C);
    out[b*FDIM + t] = (v - mean)*rstd*eln_g[t] + eln_b[t];
}

// ---------------- launch ----------------
extern "C" void kernel_launch(void* const* d_in, const int* in_sizes, int n_in,
                              void* d_out, int out_size) {
    const float* global_feat = (const float*)d_in[0];
    const float* local_feat  = (const float*)d_in[1];
    const float* Wg    = (const float*)d_in[2];
    const float* bg    = (const float*)d_in[3];
    const float* gn_g  = (const float*)d_in[4];
    const float* gn_b  = (const float*)d_in[5];
    const float* Wl    = (const float*)d_in[6];
    const float* bn_g  = (const float*)d_in[7];
    const float* bn_b  = (const float*)d_in[8];
    const float* bn_m  = (const float*)d_in[9];
    const float* bn_v  = (const float*)d_in[10];
    const float* ln_g  = (const float*)d_in[11];
    const float* ln_b  = (const float*)d_in[12];
    const float* Wq    = (const float*)d_in[13];
    const float* bq    = (const float*)d_in[14];
    const float* Wk    = (const float*)d_in[15];
    const float* bk    = (const float*)d_in[16];
    const float* Wv    = (const float*)d_in[17];
    const float* bv    = (const float*)d_in[18];
    const float* Wo    = (const float*)d_in[19];
    const float* bo    = (const float*)d_in[20];
    const float* Wgate = (const float*)d_in[21];
    const float* bgate = (const float*)d_in[22];
    const float* We1   = (const float*)d_in[23];
    const float* be1   = (const float*)d_in[24];
    const float* We2   = (const float*)d_in[25];
    const float* be2   = (const float*)d_in[26];
    const float* eln_g = (const float*)d_in[27];
    const float* eln_b = (const float*)d_in[28];
    float* out = (float*)d_out;

    // Unconditional (no static guards); not stream-ordered, capture-safe.
    (void)cudaFuncSetAttribute(local_kernel,
                               cudaFuncAttributeMaxDynamicSharedMemorySize, SMEM_TOTAL_B);

    prep_kernel<<<FDIM, CDIM>>>(Wl, bn_g, bn_b, bn_m, bn_v);
    cvt_kernel<<<4096, 256>>>(local_feat);
    global_kernel<<<BATCH, 512>>>(global_feat, Wg, bg, gn_g, gn_b, Wq, bq, Wk, bk);
    local_kernel<<<dim3(LTOK/TT, BATCH), 512, SMEM_TOTAL_B>>>(ln_g, ln_b);
    softmax_kernel<<<BATCH*NH, 256>>>();
    wsum_kernel<<<dim3(NCH, BATCH), 256>>>();
    fuse_kernel<<<BATCH, 512>>>(Wv, bv, Wo, bo, Wgate, bgate,
                                We1, be1, We2, be2, eln_g, eln_b, out);
}

// round 12
// speedup vs baseline: 1.9962x; 1.0200x over previous
#include <cuda_runtime.h>
#include <cuda_fp16.h>
#include <math.h>

// ---------------- problem constants ----------------
#define BATCH 32
#define GDIM  1024
#define CDIM  256
#define FDIM  512
#define LTOK  4096
#define NH    8
#define DHEAD 64
#define LN_EPS_C 1e-5f
#define BN_EPS_C 1e-5f
#define ATT_SCALE 0.125f     // 1/sqrt(64)
#define NCH   8              // l-chunks for weighted-sum partials
#define LCH   (LTOK/NCH)     // 512

// ---- local_kernel (fp16 tensor-core) geometry ----
#define TT    64             // tokens per CTA
#define KB    32             // k-chunk
#define ASH   72             // fp16 A row stride (halves): conflict-free ldmatrix
#define BSH   40             // fp16 B row stride (halves): conflict-free ldmatrix
#define SCRF  68             // fp32 A scratch row stride (floats)
#define SCR_F32   (KB*SCRF)              // 2176 floats per scratch buffer
#define B_HALVES  (FDIM*BSH)             // 20480 halves per B stage
#define CSTR  520            // Cs row stride (f32)
#define CS_U32  (TT*CSTR)                // 33280 floats (overlays all staging)
#define SMEM_TOTAL_B ((CS_U32 + NH*FDIM + 4*FDIM) * 4)   // 157696 B

// ---------------- device scratch (no cudaMalloc allowed) ----------------
__device__ float  g_g[BATCH*FDIM];              // normalized global feature
__device__ float  g_u[BATCH*NH*FDIM];           // per-head folded query: u = q @ Wk_head
__device__ float  g_cb[BATCH*NH];               // q . bk per head
__device__ __align__(16) __half g_Wl_h[FDIM*CDIM];   // Wl fp16, natural [f][c]
__device__ float  g_sA[FDIM];                   // folded BN scale
__device__ float  g_tA[FDIM];                   // folded BN shift
__device__ __half g_x[(size_t)BATCH*LTOK*FDIM]; // normalized local tokens (128MB)
__device__ float  g_scores[BATCH*NH*LTOK];      // logits -> softmaxed in place
__device__ float  g_wpart[BATCH*NCH*NH*FDIM];   // partial attn-weighted sums

// ---------------- helpers ----------------
__device__ __forceinline__ float block_sum_512(float v, volatile float* red) {
    int t = threadIdx.x;
#pragma unroll
    for (int o = 16; o; o >>= 1) v += __shfl_xor_sync(0xffffffffu, v, o);
    if ((t & 31) == 0) red[t >> 5] = v;
    __syncthreads();
    float r = 0.f;
    if (t < 32) {
        r = (t < 16) ? red[t] : 0.f;
#pragma unroll
        for (int o = 8; o; o >>= 1) r += __shfl_xor_sync(0xffffffffu, r, o);
        if (t == 0) red[0] = r;
    }
    __syncthreads();
    r = red[0];
    __syncthreads();
    return r;
}

__device__ __forceinline__ void mma_f16(float c[4], const unsigned a[4], unsigned b0, unsigned b1) {
    asm("mma.sync.aligned.m16n8k16.row.col.f32.f16.f16.f32 "
        "{%0,%1,%2,%3}, {%4,%5,%6,%7}, {%8,%9}, {%0,%1,%2,%3};"
        : "+f"(c[0]), "+f"(c[1]), "+f"(c[2]), "+f"(c[3])
        : "r"(a[0]), "r"(a[1]), "r"(a[2]), "r"(a[3]), "r"(b0), "r"(b1));
}

__device__ __forceinline__ void ldsm_x4(unsigned r[4], unsigned addr) {
    asm volatile("ldmatrix.sync.aligned.m8n8.x4.shared.b16 {%0,%1,%2,%3}, [%4];"
        : "=r"(r[0]), "=r"(r[1]), "=r"(r[2]), "=r"(r[3]) : "r"(addr));
}
__device__ __forceinline__ void ldsm_x4_t(unsigned r[4], unsigned addr) {
    asm volatile("ldmatrix.sync.aligned.m8n8.x4.trans.shared.b16 {%0,%1,%2,%3}, [%4];"
        : "=r"(r[0]), "=r"(r[1]), "=r"(r[2]), "=r"(r[3]) : "r"(addr));
}

__device__ __forceinline__ void cp16(void* dst_smem, const void* src) {
    unsigned d = (unsigned)__cvta_generic_to_shared(dst_smem);
    asm volatile("cp.async.cg.shared.global [%0], [%1], 16;\n" :: "r"(d), "l"(src));
}

// ---------------- kernel T: Wl -> fp16, fold BN ----------------
__global__ void prep_kernel(const float* __restrict__ Wl,
                            const float* __restrict__ bn_g, const float* __restrict__ bn_b,
                            const float* __restrict__ bn_m, const float* __restrict__ bn_v) {
    int f = blockIdx.x;          // 0..511
    int c = threadIdx.x;         // 0..255
    g_Wl_h[f*CDIM + c] = __float2half_rn(Wl[f*CDIM + c]);
    if (c == 0) {
        float s = bn_g[f] * rsqrtf(bn_v[f] + BN_EPS_C);
        g_sA[f] = s;
        g_tA[f] = bn_b[f] - bn_m[f]*s;
    }
}

// ---------------- kernel A: global branch + folded query ----------------
__global__ __launch_bounds__(512) void global_kernel(
    const float* __restrict__ gf, const float* __restrict__ Wg, const float* __restrict__ bg,
    const float* __restrict__ gn_g, const float* __restrict__ gn_b,
    const float* __restrict__ Wq, const float* __restrict__ bq,
    const float* __restrict__ Wk, const float* __restrict__ bk)
{
    __shared__ __align__(16) float sg[GDIM];
    __shared__ __align__(16) float s_g[FDIM];
    __shared__ __align__(16) float s_q[FDIM];
    __shared__ float red[16];
    int b = blockIdx.x, t = threadIdx.x;
    sg[t]       = gf[b*GDIM + t];
    sg[t + 512] = gf[b*GDIM + t + 512];
    __syncthreads();

    float acc = bg[t];
    {
        const float4* w4 = (const float4*)(Wg + (size_t)t*GDIM);
        const float4* x4 = (const float4*)sg;
#pragma unroll 8
        for (int k = 0; k < GDIM/4; k++) {
            float4 w = w4[k], x = x4[k];
            acc += w.x*x.x + w.y*x.y + w.z*x.z + w.w*x.w;
        }
    }
    float sum  = block_sum_512(acc, red);
    float sumq = block_sum_512(acc*acc, red);
    float mean = sum * (1.f/FDIM);
    float rstd = rsqrtf(sumq*(1.f/FDIM) - mean*mean + LN_EPS_C);
    float gval = (acc - mean)*rstd*gn_g[t] + gn_b[t];
    s_g[t] = gval;
    g_g[b*FDIM + t] = gval;
    __syncthreads();

    float qv = bq[t];
    {
        const float4* w4 = (const float4*)(Wq + (size_t)t*FDIM);
        const float4* x4 = (const float4*)s_g;
#pragma unroll 8
        for (int k = 0; k < FDIM/4; k++) {
            float4 w = w4[k], x = x4[k];
            qv += w.x*x.x + w.y*x.y + w.z*x.z + w.w*x.w;
        }
    }
    s_q[t] = qv;
    __syncthreads();

    int c = t;
#pragma unroll
    for (int h = 0; h < NH; h++) {
        float a = 0.f;
#pragma unroll 16
        for (int d = 0; d < DHEAD; d++)
            a += s_q[h*DHEAD + d] * __ldg(&Wk[(size_t)(h*DHEAD + d)*FDIM + c]);
        g_u[(b*NH + h)*FDIM + c] = a;
    }
    if (t < NH) {
        float a = 0.f;
#pragma unroll 16
        for (int d = 0; d < DHEAD; d++) a += s_q[t*DHEAD + d] * bk[t*DHEAD + d];
        g_cb[b*NH + t] = a;
    }
}

// ---------------- kernel B: conv1x1 GEMM (fp16 mma + ldmatrix) + BN + ReLU + LN + scores ----------------
// A arrives as RAW fp32 via cp.async into a scratch ring; a 1-step convert phase
// produces the fp16 As tile in smem (fuses the old cvt_kernel -> -201MB DRAM).
// B is fp16 weights (prep_kernel). Double-buffered; fp32 accumulate.
__global__ __launch_bounds__(512, 1) void local_kernel(
    const float* __restrict__ lf,
    const float* __restrict__ ln_g, const float* __restrict__ ln_b)
{
    extern __shared__ __align__(16) float smem[];
    // staging layout (bytes): scr0[8704] scr1[8704] B0[40960] B1[40960] As[4608] = 103936
    float*  scr0 = smem;
    float*  scr1 = smem + SCR_F32;
    __half* Bst0 = (__half*)(smem + 2*SCR_F32);
    __half* Bst1 = Bst0 + B_HALVES;
    __half* As_h = Bst1 + B_HALVES;
    // epilogue overlay
    float*  Cs   = smem;                        // [TT][CSTR]
    float*  u_s  = smem + CS_U32;               // [NH*FDIM]
    float*  prm  = smem + CS_U32 + NH*FDIM;     // sA | tA | ln_g | ln_b

    const int b  = blockIdx.y;
    const int l0 = blockIdx.x * TT;
    const int t  = threadIdx.x;
    const int wid  = t >> 5;
    const int lane = t & 31;
    const int warp_m = wid & 1;        // token half (32)
    const int warp_n = wid >> 1;       // feature group (64)
    const int qrow = lane >> 2;        // 0..7
    const int qcol = lane & 3;         // 0..3

    const float* lfb = lf + (size_t)b*CDIM*LTOK;

    // staging coords: A fp32, thread t -> row (k) = t>>4, col (token) = (t&15)*4
    const int sa_r = t >> 4;
    const int sa_c = (t & 15) * 4;

    // ldmatrix per-lane base offsets (halves)
    const int a_off = ((lane & 7) + ((lane >> 4) & 1) * 8) * ASH + ((lane >> 3) & 1) * 8;
    const int b_off = ((lane & 7) + ((lane >> 3) & 1) * 8) * BSH + ((lane >> 4) & 1) * 8;

    float acc[2][8][4];
#pragma unroll
    for (int mt = 0; mt < 2; mt++)
#pragma unroll
        for (int nt = 0; nt < 8; nt++)
#pragma unroll
            for (int i = 0; i < 4; i++) acc[mt][nt][i] = 0.f;

    // ---- stage chunk c0 (fp32 A + fp16 B) into ring slot ----
    auto issue_chunk = [&](int c0, int buf) {
        float* scr = buf ? scr1 : scr0;
        cp16(scr + sa_r*SCRF + sa_c,
             lfb + (size_t)(c0 + sa_r)*LTOK + l0 + sa_c);
        __half* bb = buf ? Bst1 : Bst0;
#pragma unroll
        for (int it = 0; it < 4; it++) {
            int idx = it*512 + t;
            int row = idx >> 2, ch = idx & 3;
            cp16(bb + row*BSH + ch*8, g_Wl_h + row*CDIM + c0 + ch*8);
        }
        asm volatile("cp.async.commit_group;\n");
    };

    issue_chunk(0,  0);
    issue_chunk(KB, 1);

    const unsigned a_smem = (unsigned)__cvta_generic_to_shared(As_h);

#pragma unroll 1
    for (int ci = 0; ci < CDIM/KB; ci++) {
        if (ci < CDIM/KB - 1) asm volatile("cp.async.wait_group 1;\n");
        else                  asm volatile("cp.async.wait_group 0;\n");
        __syncthreads();

        // convert this chunk's fp32 A scratch -> fp16 As tile
        {
            const float* scr = (ci & 1) ? scr1 : scr0;
            float4 v = *(const float4*)(scr + sa_r*SCRF + sa_c);
            __half2* d = (__half2*)(As_h + sa_r*ASH + sa_c);
            d[0] = __floats2half2_rn(v.x, v.y);
            d[1] = __floats2half2_rn(v.z, v.w);
        }
        __syncthreads();

        unsigned b_smem = (unsigned)__cvta_generic_to_shared((ci & 1) ? Bst1 : Bst0);

#pragma unroll
        for (int kt = 0; kt < 2; kt++) {
            const int kk = kt * 16;
            unsigned afr[2][4], bfr[4][4];
#pragma unroll
            for (int mt = 0; mt < 2; mt++) {
                int m0 = warp_m*32 + mt*16;
                ldsm_x4_t(afr[mt], a_smem + (a_off + kk*ASH + m0) * 2);
            }
#pragma unroll
            for (int np = 0; np < 4; np++) {
                int n0 = warp_n*64 + np*16;
                ldsm_x4(bfr[np], b_smem + (b_off + n0*BSH + kk) * 2);
            }
#pragma unroll
            for (int mt = 0; mt < 2; mt++)
#pragma unroll
                for (int nt = 0; nt < 8; nt++) {
                    int np = nt >> 1, odd = nt & 1;
                    mma_f16(acc[mt][nt], afr[mt], bfr[np][odd], bfr[np][2 + odd]);
                }
        }
        __syncthreads();   // done reading this ring slot (scratch + B + As)

        if (ci + 2 < CDIM/KB) issue_chunk((ci + 2)*KB, ci & 1);
    }

    // ---- spill accumulators to Cs (mma layout -> [token][feature]) ----
#pragma unroll
    for (int mt = 0; mt < 2; mt++) {
#pragma unroll
        for (int nt = 0; nt < 8; nt++) {
            int row = warp_m*32 + mt*16 + qrow;
            int col = warp_n*64 + nt*8 + 2*qcol;
            *(float2*)&Cs[ row     *CSTR + col] = make_float2(acc[mt][nt][0], acc[mt][nt][1]);
            *(float2*)&Cs[(row + 8)*CSTR + col] = make_float2(acc[mt][nt][2], acc[mt][nt][3]);
        }
    }
    // load u and per-feature params (disjoint smem regions)
#pragma unroll
    for (int i = 0; i < 8; i++) u_s[t + 512*i] = g_u[(size_t)b*NH*FDIM + t + 512*i];
    prm[t]        = g_sA[t];
    prm[512 + t]  = g_tA[t];
    prm[1024 + t] = ln_g[t];
    prm[1536 + t] = ln_b[t];
    __syncthreads();

    // ---- per-token BN + ReLU + LN, fp16 stash (warp wid owns tokens wid*4..wid*4+3) ----
#pragma unroll
    for (int tok = 0; tok < 4; tok++) {
        int row = wid*4 + tok;
        float v[16];
        float s = 0.f, ss = 0.f;
#pragma unroll
        for (int j = 0; j < 16; j++) {
            int f = lane + 32*j;
            float r = fmaxf(fmaf(Cs[row*CSTR + f], prm[f], prm[512 + f]), 0.f);
            v[j] = r; s += r; ss += r*r;
        }
#pragma unroll
        for (int o = 16; o; o >>= 1) {
            s  += __shfl_xor_sync(0xffffffffu, s,  o);
            ss += __shfl_xor_sync(0xffffffffu, ss, o);
        }
        float mean = s * (1.f/FDIM);
        float rstd = rsqrtf(ss*(1.f/FDIM) - mean*mean + LN_EPS_C);
        __half* dst = g_x + ((size_t)(b*LTOK + l0 + row))*FDIM;
#pragma unroll
        for (int j = 0; j < 16; j++) {
            int f = lane + 32*j;
            float nx = fmaf((v[j] - mean)*rstd, prm[1024 + f], prm[1536 + f]);
            Cs[row*CSTR + f] = nx;
            dst[f] = __float2half_rn(nx);
        }
    }

    // ---- scores: p[tok][h] = x . u[h]  (1 LDS-u per 4 FMA) ----
    float p[4][8];
#pragma unroll
    for (int a = 0; a < 4; a++)
#pragma unroll
        for (int h = 0; h < 8; h++) p[a][h] = 0.f;
#pragma unroll
    for (int j = 0; j < 16; j++) {
        int f = lane + 32*j;
        float xv[4];
#pragma unroll
        for (int a = 0; a < 4; a++) xv[a] = Cs[(wid*4 + a)*CSTR + f];
#pragma unroll
        for (int h = 0; h < 8; h++) {
            float uv = u_s[h*FDIM + f];
#pragma unroll
            for (int a = 0; a < 4; a++) p[a][h] = fmaf(xv[a], uv, p[a][h]);
        }
    }
#pragma unroll
    for (int a = 0; a < 4; a++)
#pragma unroll
        for (int h = 0; h < 8; h++)
#pragma unroll
            for (int o = 16; o; o >>= 1)
                p[a][h] += __shfl_xor_sync(0xffffffffu, p[a][h], o);

    {
        int hh = lane & 7, tk = lane >> 3;
        float v = 0.f;
#pragma unroll
        for (int a = 0; a < 4; a++)
#pragma unroll
            for (int h = 0; h < 8; h++)
                if (a == tk && h == hh) v = p[a][h];
        g_scores[(size_t)(b*NH + hh)*LTOK + l0 + wid*4 + tk] =
            (v + g_cb[b*NH + hh]) * ATT_SCALE;
    }
}

// ---------------- kernel C: softmax over L per (b,h) ----------------
__global__ __launch_bounds__(256) void softmax_kernel() {
    int r = blockIdx.x;                      // b*8+h
    float* row = g_scores + (size_t)r*LTOK;
    __shared__ float red[8];
    int t = threadIdx.x;
    float v[16];
    float mx = -1e30f;
#pragma unroll
    for (int i = 0; i < 16; i++) { v[i] = row[t + 256*i]; mx = fmaxf(mx, v[i]); }
#pragma unroll
    for (int o = 16; o; o >>= 1) mx = fmaxf(mx, __shfl_xor_sync(0xffffffffu, mx, o));
    if ((t & 31) == 0) red[t >> 5] = mx;
    __syncthreads();
    if (t < 32) {
        float m = (t < 8) ? red[t] : -1e30f;
#pragma unroll
        for (int o = 4; o; o >>= 1) m = fmaxf(m, __shfl_xor_sync(0xffffffffu, m, o));
        if (t == 0) red[0] = m;
    }
    __syncthreads();
    mx = red[0];
    __syncthreads();
    float s = 0.f;
#pragma unroll
    for (int i = 0; i < 16; i++) { v[i] = __expf(v[i] - mx); s += v[i]; }
#pragma unroll
    for (int o = 16; o; o >>= 1) s += __shfl_xor_sync(0xffffffffu, s, o);
    if ((t & 31) == 0) red[t >> 5] = s;
    __syncthreads();
    if (t < 32) {
        float m = (t < 8) ? red[t] : 0.f;
#pragma unroll
        for (int o = 4; o; o >>= 1) m += __shfl_xor_sync(0xffffffffu, m, o);
        if (t == 0) red[0] = m;
    }
    __syncthreads();
    float inv = 1.f / red[0];
#pragma unroll
    for (int i = 0; i < 16; i++) row[t + 256*i] = v[i] * inv;
}

// ---------------- kernel D: w_part[b,ch,h,c] = sum_l attn * x ----------------
__global__ __launch_bounds__(256) void wsum_kernel() {
    int b = blockIdx.y, ch = blockIdx.x;
    int l0 = ch * LCH;
    __shared__ float at[NH][LCH];   // 16KB
    int t = threadIdx.x;
    for (int i = t; i < NH*LCH; i += 256) {
        int h = i >> 9, l = i & 511;
        at[h][l] = g_scores[(size_t)(b*NH + h)*LTOK + l0 + l];
    }
    __syncthreads();
    float acc[16];
#pragma unroll
    for (int i = 0; i < 16; i++) acc[i] = 0.f;
    const __half2* xp = (const __half2*)g_x + (size_t)(b*LTOK + l0)*(FDIM/2) + t;
#pragma unroll 4
    for (int l = 0; l < LCH; l++) {
        float2 xv = __half22float2(xp[(size_t)l*(FDIM/2)]);
#pragma unroll
        for (int h = 0; h < NH; h++) {
            float a = at[h][l];
            acc[2*h]   = fmaf(a, xv.x, acc[2*h]);
            acc[2*h+1] = fmaf(a, xv.y, acc[2*h+1]);
        }
    }
    float* wp = g_wpart + (size_t)((b*NCH + ch)*NH)*FDIM;
#pragma unroll
    for (int h = 0; h < NH; h++)
        *(float2*)&wp[h*FDIM + 2*t] = make_float2(acc[2*h], acc[2*h+1]);
}

// ---------------- kernel E: o/attended/gate/MLP/LN ----------------
__global__ __launch_bounds__(512) void fuse_kernel(
    const float* __restrict__ Wv, const float* __restrict__ bv,
    const float* __restrict__ Wo, const float* __restrict__ bo,
    const float* __restrict__ Wgate, const float* __restrict__ bgate,
    const float* __restrict__ We1, const float* __restrict__ be1,
    const float* __restrict__ We2, const float* __restrict__ be2,
    const float* __restrict__ eln_g, const float* __restrict__ eln_b,
    float* __restrict__ out)
{
    __shared__ __align__(16) float w_s[NH*FDIM];   // 16KB
    __shared__ __align__(16) float o_s[FDIM];
    __shared__ __align__(16) float att_s[FDIM];
    __shared__ __align__(16) float gs[FDIM];
    __shared__ __align__(16) float fu[FDIM];
    __shared__ __align__(16) float h1[2*FDIM];
    __shared__ float red[16];
    int b = blockIdx.x, t = threadIdx.x;

    for (int i = t; i < NH*FDIM; i += 512) {
        float s = 0.f;
#pragma unroll
        for (int ch = 0; ch < NCH; ch++)
            s += g_wpart[(size_t)((b*NCH + ch)*NH)*FDIM + i];
        w_s[i] = s;
    }
    gs[t] = g_g[b*FDIM + t];
    __syncthreads();

    {
        int h = t >> 6;
        float a = bv[t];
        const float4* wr = (const float4*)(Wv + (size_t)t*FDIM);
        const float4* ws = (const float4*)(w_s + h*FDIM);
#pragma unroll 8
        for (int k = 0; k < FDIM/4; k++) {
            float4 w = wr[k], x = ws[k];
            a += w.x*x.x + w.y*x.y + w.z*x.z + w.w*x.w;
        }
        o_s[t] = a;
    }
    __syncthreads();

    {
        float a = bo[t];
        const float4* wr = (const float4*)(Wo + (size_t)t*FDIM);
        const float4* xs = (const float4*)o_s;
#pragma unroll 8
        for (int k = 0; k < FDIM/4; k++) {
            float4 w = wr[k], x = xs[k];
            a += w.x*x.x + w.y*x.y + w.z*x.z + w.w*x.w;
        }
        att_s[t] = a;
    }
    __syncthreads();

    {
        float z = bgate[t];
        const float4* wr = (const float4*)(Wgate + (size_t)t*2*FDIM);
        const float4* xg = (const float4*)gs;
        const float4* xa = (const float4*)att_s;
#pragma unroll 8
        for (int k = 0; k < FDIM/4; k++) {
            float4 w = wr[k], x = xg[k];
            z += w.x*x.x + w.y*x.y + w.z*x.z + w.w*x.w;
        }
#pragma unroll 8
        for (int k = 0; k < FDIM/4; k++) {
            float4 w = wr[FDIM/4 + k], x = xa[k];
            z += w.x*x.x + w.y*x.y + w.z*x.z + w.w*x.w;
        }
        float gate = 1.f / (1.f + expf(-z));
        fu[t] = gate*gs[t] + (1.f - gate)*att_s[t];
    }
    __syncthreads();

#pragma unroll
    for (int rr = 0; rr < 2; rr++) {
        int j = t + 512*rr;
        float a = be1[j];
        const float4* wr = (const float4*)(We1 + (size_t)j*FDIM);
        const float4* xs = (const float4*)fu;
#pragma unroll 8
        for (int k = 0; k < FDIM/4; k++) {
            float4 w = wr[k], x = xs[k];
            a += w.x*x.x + w.y*x.y + w.z*x.z + w.w*x.w;
        }
        h1[j] = 0.5f * a * (1.f + erff(a * 0.70710678118654752f));
    }
    __syncthreads();

    float v = be2[t];
    {
        const float4* wr = (const float4*)(We2 + (size_t)t*2*FDIM);
        const float4* xs = (const float4*)h1;
#pragma unroll 8
        for (int k = 0; k < 2*FDIM/4; k++) {
            float4 w = wr[k], x = xs[k];
            v += w.x*x.x + w.y*x.y + w.z*x.z + w.w*x.w;
        }
    }
    float sum  = block_sum_512(v, red);
    float sumq = block_sum_512(v*v, red);
    float mean = sum * (1.f/FDIM);
    float rstd = rsqrtf(sumq*(1.f/FDIM) - mean*mean + LN_EPS_C);
    out[b*FDIM + t] = (v - mean)*rstd*eln_g[t] + eln_b[t];
}

// ---------------- launch ----------------
extern "C" void kernel_launch(void* const* d_in, const int* in_sizes, int n_in,
                              void* d_out, int out_size) {
    const float* global_feat = (const float*)d_in[0];
    const float* local_feat  = (const float*)d_in[1];
    const float* Wg    = (const float*)d_in[2];
    const float* bg    = (const float*)d_in[3];
    const float* gn_g  = (const float*)d_in[4];
    const float* gn_b  = (const float*)d_in[5];
    const float* Wl    = (const float*)d_in[6];
    const float* bn_g  = (const float*)d_in[7];
    const float* bn_b  = (const float*)d_in[8];
    const float* bn_m  = (const float*)d_in[9];
    const float* bn_v  = (const float*)d_in[10];
    const float* ln_g  = (const float*)d_in[11];
    const float* ln_b  = (const float*)d_in[12];
    const float* Wq    = (const float*)d_in[13];
    const float* bq    = (const float*)d_in[14];
    const float* Wk    = (const float*)d_in[15];
    const float* bk    = (const float*)d_in[16];
    const float* Wv    = (const float*)d_in[17];
    const float* bv    = (const float*)d_in[18];
    const float* Wo    = (const float*)d_in[19];
    const float* bo    = (const float*)d_in[20];
    const float* Wgate = (const float*)d_in[21];
    const float* bgate = (const float*)d_in[22];
    const float* We1   = (const float*)d_in[23];
    const float* be1   = (const float*)d_in[24];
    const float* We2   = (const float*)d_in[25];
    const float* be2   = (const float*)d_in[26];
    const float* eln_g = (const float*)d_in[27];
    const float* eln_b = (const float*)d_in[28];
    float* out = (float*)d_out;

    // Unconditional (no static guards); not stream-ordered, capture-safe.
    (void)cudaFuncSetAttribute(local_kernel,
                               cudaFuncAttributeMaxDynamicSharedMemorySize, SMEM_TOTAL_B);

    prep_kernel<<<FDIM, CDIM>>>(Wl, bn_g, bn_b, bn_m, bn_v);
    global_kernel<<<BATCH, 512>>>(global_feat, Wg, bg, gn_g, gn_b, Wq, bq, Wk, bk);
    local_kernel<<<dim3(LTOK/TT, BATCH), 512, SMEM_TOTAL_B>>>(local_feat, ln_g, ln_b);
    softmax_kernel<<<BATCH*NH, 256>>>();
    wsum_kernel<<<dim3(NCH, BATCH), 256>>>();
    fuse_kernel<<<BATCH, 512>>>(Wv, bv, Wo, bo, Wgate, bgate,
                                We1, be1, We2, be2, eln_g, eln_b, out);
}